// round 8
// baseline (speedup 1.0000x reference)
#include <cuda_runtime.h>
#include <cuda_fp16.h>
#include <cstdint>
#include <math.h>

#define D_MODEL 1024
#define N_HEADS 16
#define D_HEAD  64
#define B_SZ    4
#define SEQ     2048
#define M_ROWS  (B_SZ * SEQ)   // 8192
#define K3      (3 * D_MODEL)  // 3072
#define K2      (2 * D_MODEL)  // 2048
#define WROW    D_MODEL
#define NQT     (SEQ / 128)    // 16

// ---------------- scratch (__device__ globals) ------------------------------
__device__ float  g_qkv[M_ROWS * K3];
__device__ __half g_xh [M_ROWS * K2];
__device__ __half g_aoh[M_ROWS * K2];
__device__ __half g_wh [4 * D_MODEL * D_MODEL];
__device__ __half g_Qp [B_SZ * N_HEADS * NQT * 16384];
__device__ __half g_KVp[B_SZ * N_HEADS * NQT * 24576];

// ---------------- helpers ----------------------------------------------------
__device__ __forceinline__ uint32_t smem_u32(const void* p) {
    uint32_t a;
    asm("{ .reg .u64 t; cvta.to.shared.u64 t, %1; cvt.u32.u64 %0, t; }" : "=r"(a) : "l"(p));
    return a;
}
__device__ __forceinline__ void cp_async16(uint32_t s, const void* g) {
    asm volatile("cp.async.cg.shared.global [%0], [%1], 16;" :: "r"(s), "l"(g));
}
#define CP_COMMIT() asm volatile("cp.async.commit_group;" ::: "memory")
#define CP_WAIT0()  asm volatile("cp.async.wait_group 0;" ::: "memory")
#define CP_WAIT2()  asm volatile("cp.async.wait_group 2;" ::: "memory")

__device__ __forceinline__ void ldsm4(uint32_t& r0, uint32_t& r1, uint32_t& r2, uint32_t& r3,
                                      uint32_t addr) {
    asm volatile("ldmatrix.sync.aligned.m8n8.x4.shared.b16 {%0,%1,%2,%3}, [%4];"
                 : "=r"(r0), "=r"(r1), "=r"(r2), "=r"(r3) : "r"(addr));
}
__device__ __forceinline__ void mma16816h(float* c, uint32_t a0, uint32_t a1,
                                          uint32_t a2, uint32_t a3,
                                          uint32_t b0, uint32_t b1) {
    asm volatile("mma.sync.aligned.m16n8k16.row.col.f32.f16.f16.f32 "
                 "{%0,%1,%2,%3}, {%4,%5,%6,%7}, {%8,%9}, {%0,%1,%2,%3};"
                 : "+f"(c[0]), "+f"(c[1]), "+f"(c[2]), "+f"(c[3])
                 : "r"(a0), "r"(a1), "r"(a2), "r"(a3), "r"(b0), "r"(b1));
}
__device__ __forceinline__ uint32_t swz(int row, int c) {          // 64B rows
    return (uint32_t)(row * 64 + ((c ^ ((row >> 1) & 3)) << 4));
}
__device__ __forceinline__ uint32_t swz128(int row, int c) {       // 128B rows
    return (uint32_t)(row * 128 + ((c ^ (row & 7)) << 4));
}
__device__ __forceinline__ uint32_t swzV(int row, int c) {         // 256B rows
    return (uint32_t)(row * 256 + ((c ^ (row & 7)) << 4));
}
__device__ __forceinline__ uint32_t pack_h2(float a, float b) {
    __half2 h = __floats2half2_rn(a, b);
    return *(uint32_t*)&h;
}

// ---------------- fp32 -> fp16 [hi|lo] split (pitch K2) ----------------------
__global__ void split2(const float* __restrict__ src, __half* __restrict__ dst, int n4)
{
    int i = blockIdx.x * 256 + threadIdx.x;
    if (i >= n4) return;
    int r = i >> 8;
    int c = (i & 255) * 4;
    float4 v = ((const float4*)src)[i];
    float f[4] = {v.x, v.y, v.z, v.w};
    ushort hb[4], lb[4];
#pragma unroll
    for (int e = 0; e < 4; e++) {
        __half hh = __float2half_rn(f[e]);
        hb[e] = __half_as_ushort(hh);
        lb[e] = __half_as_ushort(__float2half_rn(f[e] - __half2float(hh)));
    }
    size_t base = (size_t)r * K2 + c;
    *(ushort4*)(dst + base)           = *(ushort4*)hb;
    *(ushort4*)(dst + base + D_MODEL) = *(ushort4*)lb;
}

__global__ void convh4(const float* __restrict__ w0, const float* __restrict__ w1,
                       const float* __restrict__ w2, const float* __restrict__ w3,
                       __half* __restrict__ dst, int n4)
{
    int i = blockIdx.x * 256 + threadIdx.x;
    if (i >= n4) return;
    const float* srcs[4] = {w0, w1, w2, w3};
    const float* src = srcs[blockIdx.y];
    __half* d = dst + (size_t)blockIdx.y * D_MODEL * D_MODEL;
    float4 v = ((const float4*)src)[i];
    ushort hb[4] = {
        __half_as_ushort(__float2half_rn(v.x)),
        __half_as_ushort(__float2half_rn(v.y)),
        __half_as_ushort(__float2half_rn(v.z)),
        __half_as_ushort(__float2half_rn(v.w))};
    *(ushort4*)(d + (size_t)i * 4) = *(ushort4*)hb;
}

// ---------------- fp16 NT GEMM, BM=128 x BN=256, 512 threads -----------------
#define BM 128
#define BN 256
#define BKT 32
#define STAGES 4
#define STG_A 8192                     // 128 rows x 64B
#define STG_B 16384                    // 256 rows x 64B
#define STAGE_BYTES (STG_A + STG_B)    // 24576
#define G_SMEM (STAGES * STAGE_BYTES)  // 98304
#define NKT (K2 / BKT)                 // 64

__global__ __launch_bounds__(512, 1)
void gemm_f16(const __half* __restrict__ A, const __half* __restrict__ B,
              float* __restrict__ C, int cpitch)
{
    extern __shared__ __align__(128) char sm[];
    const uint32_t sbase = smem_u32(sm);
    const int tid  = threadIdx.x;
    const int lane = tid & 31;
    const int wid  = tid >> 5;           // 0..15
    const int wm   = wid & 3;            // 4 m-groups x 32 rows
    const int wn   = wid >> 2;           // 4 n-groups x 64 cols
    const int m0 = blockIdx.y * BM;
    const int n0 = blockIdx.x * BN;

    // A: 512 x 16B chunks, 1/thread. B: 1024 chunks, 2/thread.
    const int ar = tid >> 2,  ac = tid & 3;
    const int br0 = tid >> 2, bc0 = tid & 3;          // rows 0..127
    const int br1 = (tid + 512) >> 2, bc1 = tid & 3;  // rows 128..255

    const __half* Ag  = A + (size_t)(m0 + ar) * K2 + ac * 8;
    const __half* Bg0 = B + (size_t)(n0 + br0) * WROW + bc0 * 8;
    const __half* Bg1 = B + (size_t)(n0 + br1) * WROW + bc1 * 8;
    const uint32_t sA = swz(ar, ac);
    const uint32_t sB0 = swz(br0, bc0), sB1 = swz(br1, bc1);

    float acc[2][8][4];
#pragma unroll
    for (int i = 0; i < 2; i++)
#pragma unroll
        for (int j = 0; j < 8; j++)
#pragma unroll
            for (int q = 0; q < 4; q++) acc[i][j][q] = 0.f;

#pragma unroll
    for (int s = 0; s < STAGES - 1; s++) {
        uint32_t st = sbase + s * STAGE_BYTES;
        int ko = s * BKT;
        cp_async16(st + sA,          Ag  + ko);
        cp_async16(st + STG_A + sB0, Bg0 + (ko & 1023));
        cp_async16(st + STG_A + sB1, Bg1 + (ko & 1023));
        CP_COMMIT();
    }

    const int aRow = wm * 32 + (lane & 15);
    const int aCsel = lane >> 4;
    const int bRow = wn * 64 + (lane & 7) + ((lane >> 4) << 3);
    const int bCsel = (lane >> 3) & 1;

    for (int kt = 0; kt < NKT; kt++) {
        CP_WAIT2();
        __syncthreads();

        if (kt + STAGES - 1 < NKT) {
            int s = (kt + STAGES - 1) % STAGES;
            int ko = (kt + STAGES - 1) * BKT;
            uint32_t st = sbase + s * STAGE_BYTES;
            cp_async16(st + sA,          Ag  + ko);
            cp_async16(st + STG_A + sB0, Bg0 + (ko & 1023));
            cp_async16(st + STG_A + sB1, Bg1 + (ko & 1023));
        }
        CP_COMMIT();

        const uint32_t stA = sbase + (kt % STAGES) * STAGE_BYTES;
        const uint32_t stB = stA + STG_A;

#pragma unroll
        for (int k16 = 0; k16 < 2; k16++) {
            const int kc = k16 * 2;
            uint32_t af[2][4];
#pragma unroll
            for (int i = 0; i < 2; i++) {
                int r = aRow + i * 16;
                ldsm4(af[i][0], af[i][1], af[i][2], af[i][3],
                      stA + swz(r, kc + aCsel));
            }
            uint32_t bf[4][4];
#pragma unroll
            for (int j = 0; j < 4; j++) {
                int r = bRow + j * 16;
                ldsm4(bf[j][0], bf[j][1], bf[j][2], bf[j][3],
                      stB + swz(r, kc + bCsel));
            }
#pragma unroll
            for (int i = 0; i < 2; i++)
#pragma unroll
                for (int j = 0; j < 4; j++) {
                    mma16816h(acc[i][2*j+0], af[i][0], af[i][1], af[i][2], af[i][3],
                              bf[j][0], bf[j][1]);
                    mma16816h(acc[i][2*j+1], af[i][0], af[i][1], af[i][2], af[i][3],
                              bf[j][2], bf[j][3]);
                }
        }
    }

    const int gid = lane >> 2, q = lane & 3;
#pragma unroll
    for (int i = 0; i < 2; i++) {
        int r0 = m0 + wm * 32 + i * 16 + gid;
#pragma unroll
        for (int j = 0; j < 8; j++) {
            int col = n0 + wn * 64 + j * 8 + q * 2;
            *(float2*)(C + (size_t)r0 * cpitch + col) =
                make_float2(acc[i][j][0], acc[i][j][1]);
            *(float2*)(C + (size_t)(r0 + 8) * cpitch + col) =
                make_float2(acc[i][j][2], acc[i][j][3]);
        }
    }
}

// ---------------------------------------------------------------------------
// prep: fp32 qkv -> pre-swizzled fp16 tile images (unchanged, proven)
// ---------------------------------------------------------------------------
__global__ __launch_bounds__(256, 4)
void prep_attn()
{
    const int tid = threadIdx.x;
    const int t = blockIdx.x, h = blockIdx.y, b = blockIdx.z;
    const int r0 = t * 128;
    const size_t bh = (size_t)(b * N_HEADS + h) * NQT + t;

    char* qdst  = (char*)(g_Qp  + bh * 16384);
    char* kvdst = (char*)(g_KVp + bh * 24576);

    const float* Qg = g_qkv + (size_t)(b * SEQ + r0) * K3 + h * D_HEAD;
    const float* Kg = Qg + D_MODEL;
#pragma unroll
    for (int it = 0; it < 4; it++) {
        int idx = tid + it * 256;
        int r = idx >> 3, c = idx & 7;
        uint32_t off = swz128(r, c);
        {
            const float* p = Qg + (size_t)r * K3 + c * 8;
            float4 u = *(const float4*)p;
            float4 v = *(const float4*)(p + 4);
            float f[8] = {u.x*0.125f, u.y*0.125f, u.z*0.125f, u.w*0.125f,
                          v.x*0.125f, v.y*0.125f, v.z*0.125f, v.w*0.125f};
            ushort hib[8], lob[8];
#pragma unroll
            for (int e = 0; e < 8; e++) {
                __half hh = __float2half_rn(f[e]);
                hib[e] = __half_as_ushort(hh);
                lob[e] = __half_as_ushort(__float2half_rn(f[e] - __half2float(hh)));
            }
            *(uint4*)(qdst + off)         = *(uint4*)hib;
            *(uint4*)(qdst + 16384 + off) = *(uint4*)lob;
        }
        {
            const float* p = Kg + (size_t)r * K3 + c * 8;
            float4 u = *(const float4*)p;
            float4 v = *(const float4*)(p + 4);
            float f[8] = {u.x, u.y, u.z, u.w, v.x, v.y, v.z, v.w};
            ushort hib[8], lob[8];
#pragma unroll
            for (int e = 0; e < 8; e++) {
                __half hh = __float2half_rn(f[e]);
                hib[e] = __half_as_ushort(hh);
                lob[e] = __half_as_ushort(__float2half_rn(f[e] - __half2float(hh)));
            }
            *(uint4*)(kvdst + off)         = *(uint4*)hib;
            *(uint4*)(kvdst + 16384 + off) = *(uint4*)lob;
        }
    }
    const float* Vg = Qg + 2 * D_MODEL;
#pragma unroll
    for (int it = 0; it < 4; it++) {
        int idx = tid + it * 256;
        int d = idx & 63, jc = idx >> 6;
        ushort vb[8];
#pragma unroll
        for (int jj = 0; jj < 8; jj++)
            vb[jj] = __half_as_ushort(
                __float2half_rn(Vg[(size_t)(jc * 8 + jj) * K3 + d]));
        *(uint4*)(kvdst + 32768 + swzV(d, jc)) = *(uint4*)vb;
    }
}

// ---------------------------------------------------------------------------
// Flash attention (round-7 proven): cp.async + ldsm + HMMA, K/V double-buffer
// ---------------------------------------------------------------------------
#define SM_Q   0
#define SM_ST  32768
#define STG    49152
#define A_SMEM (32768 + 2 * 49152)

__global__ __launch_bounds__(256, 1)
void flash_attn_f16()
{
    extern __shared__ __align__(128) char smc[];
    const uint32_t sb = smem_u32(smc);
    const int tid  = threadIdx.x;
    const int lane = tid & 31;
    const int wid  = tid >> 5;
    const int gid  = lane >> 2;
    const int qq   = lane & 3;
    const int qt = gridDim.x - 1 - blockIdx.x;
    const int h  = blockIdx.y;
    const int b  = blockIdx.z;
    const int q0 = qt * 128;
    const size_t bhbase = (size_t)(b * N_HEADS + h) * NQT;

    {
        const char* qs = (const char*)(g_Qp + (bhbase + qt) * 16384);
#pragma unroll
        for (int i = 0; i < 8; i++) {
            uint32_t off = (tid + i * 256) * 16;
            cp_async16(sb + SM_Q + off, qs + off);
        }
        const char* kvs = (const char*)(g_KVp + bhbase * 24576);
#pragma unroll
        for (int i = 0; i < 12; i++) {
            uint32_t off = (tid + i * 256) * 16;
            cp_async16(sb + SM_ST + off, kvs + off);
        }
        CP_COMMIT();
    }
    CP_WAIT0();
    __syncthreads();

    const int aRow = wid * 16 + (lane & 15);
    const int aCsel = lane >> 4;
    uint32_t qh[4][4], ql[4][4];
#pragma unroll
    for (int kt2 = 0; kt2 < 4; kt2++) {
        ldsm4(qh[kt2][0], qh[kt2][1], qh[kt2][2], qh[kt2][3],
              sb + SM_Q + swz128(aRow, kt2 * 2 + aCsel));
        ldsm4(ql[kt2][0], ql[kt2][1], ql[kt2][2], ql[kt2][3],
              sb + SM_Q + 16384 + swz128(aRow, kt2 * 2 + aCsel));
    }

    float m0r = -1e30f, m1r = -1e30f, l0r = 0.f, l1r = 0.f;
    float oacc[8][4];
#pragma unroll
    for (int j = 0; j < 8; j++)
#pragma unroll
        for (int q2 = 0; q2 < 4; q2++) oacc[j][q2] = 0.f;

    const int bRowBase = (lane & 7) + ((lane >> 4) << 3);
    const int bCsel = (lane >> 3) & 1;
    const int row0 = wid * 16 + gid;
    const int row1 = row0 + 8;

    for (int t = 0; t <= qt; t++) {
        if (t > 0) {
            CP_WAIT0();
            __syncthreads();
        }
        if (t < qt) {
            const char* kvs = (const char*)(g_KVp + (bhbase + t + 1) * 24576);
            uint32_t dst = sb + SM_ST + ((t + 1) & 1) * STG;
#pragma unroll
            for (int i = 0; i < 12; i++) {
                uint32_t off = (tid + i * 256) * 16;
                cp_async16(dst + off, kvs + off);
            }
            CP_COMMIT();
        }

        const uint32_t kb = sb + SM_ST + (t & 1) * STG;
        const uint32_t lb = kb + 16384;
        const uint32_t vbse = kb + 32768;

        float sacc[16][4];
#pragma unroll
        for (int j = 0; j < 16; j++)
#pragma unroll
            for (int q2 = 0; q2 < 4; q2++) sacc[j][q2] = 0.f;

#pragma unroll
        for (int kt2 = 0; kt2 < 4; kt2++) {
#pragma unroll
            for (int jt2 = 0; jt2 < 8; jt2++) {
                int r = jt2 * 16 + bRowBase;
                uint32_t kc = kt2 * 2 + bCsel;
                uint32_t bh4[4], bl4[4];
                ldsm4(bh4[0], bh4[1], bh4[2], bh4[3], kb + swz128(r, kc));
                ldsm4(bl4[0], bl4[1], bl4[2], bl4[3], lb + swz128(r, kc));
                mma16816h(sacc[2*jt2],   qh[kt2][0], qh[kt2][1], qh[kt2][2], qh[kt2][3], bh4[0], bh4[1]);
                mma16816h(sacc[2*jt2+1], qh[kt2][0], qh[kt2][1], qh[kt2][2], qh[kt2][3], bh4[2], bh4[3]);
                mma16816h(sacc[2*jt2],   ql[kt2][0], ql[kt2][1], ql[kt2][2], ql[kt2][3], bh4[0], bh4[1]);
                mma16816h(sacc[2*jt2+1], ql[kt2][0], ql[kt2][1], ql[kt2][2], ql[kt2][3], bh4[2], bh4[3]);
                mma16816h(sacc[2*jt2],   qh[kt2][0], qh[kt2][1], qh[kt2][2], qh[kt2][3], bl4[0], bl4[1]);
                mma16816h(sacc[2*jt2+1], qh[kt2][0], qh[kt2][1], qh[kt2][2], qh[kt2][3], bl4[2], bl4[3]);
            }
        }

        if (t == qt) {
#pragma unroll
            for (int j = 0; j < 16; j++) {
                int c0 = j * 8 + qq * 2;
                if (c0 > row0)     sacc[j][0] = -1e30f;
                if (c0 + 1 > row0) sacc[j][1] = -1e30f;
                if (c0 > row1)     sacc[j][2] = -1e30f;
                if (c0 + 1 > row1) sacc[j][3] = -1e30f;
            }
        }

        float mx0 = -1e30f, mx1 = -1e30f;
#pragma unroll
        for (int j = 0; j < 16; j++) {
            mx0 = fmaxf(mx0, fmaxf(sacc[j][0], sacc[j][1]));
            mx1 = fmaxf(mx1, fmaxf(sacc[j][2], sacc[j][3]));
        }
        mx0 = fmaxf(mx0, __shfl_xor_sync(0xffffffffu, mx0, 1));
        mx0 = fmaxf(mx0, __shfl_xor_sync(0xffffffffu, mx0, 2));
        mx1 = fmaxf(mx1, __shfl_xor_sync(0xffffffffu, mx1, 1));
        mx1 = fmaxf(mx1, __shfl_xor_sync(0xffffffffu, mx1, 2));

        float mn0 = fmaxf(m0r, mx0), mn1 = fmaxf(m1r, mx1);
        float cr0 = __expf(m0r - mn0), cr1 = __expf(m1r - mn1);
        float sum0 = 0.f, sum1 = 0.f;
#pragma unroll
        for (int j = 0; j < 16; j++) {
            sacc[j][0] = __expf(sacc[j][0] - mn0);
            sacc[j][1] = __expf(sacc[j][1] - mn0);
            sacc[j][2] = __expf(sacc[j][2] - mn1);
            sacc[j][3] = __expf(sacc[j][3] - mn1);
            sum0 += sacc[j][0] + sacc[j][1];
            sum1 += sacc[j][2] + sacc[j][3];
        }
        sum0 += __shfl_xor_sync(0xffffffffu, sum0, 1);
        sum0 += __shfl_xor_sync(0xffffffffu, sum0, 2);
        sum1 += __shfl_xor_sync(0xffffffffu, sum1, 1);
        sum1 += __shfl_xor_sync(0xffffffffu, sum1, 2);

        l0r = l0r * cr0 + sum0;  m0r = mn0;
        l1r = l1r * cr1 + sum1;  m1r = mn1;
#pragma unroll
        for (int j = 0; j < 8; j++) {
            oacc[j][0] *= cr0; oacc[j][1] *= cr0;
            oacc[j][2] *= cr1; oacc[j][3] *= cr1;
        }

#pragma unroll
        for (int kt2 = 0; kt2 < 8; kt2++) {
            const int jA = 2 * kt2, jB = 2 * kt2 + 1;
            uint32_t ph[4], pl[4];
            ph[0] = pack_h2(sacc[jA][0], sacc[jA][1]);
            ph[1] = pack_h2(sacc[jA][2], sacc[jA][3]);
            ph[2] = pack_h2(sacc[jB][0], sacc[jB][1]);
            ph[3] = pack_h2(sacc[jB][2], sacc[jB][3]);
            {
                __half2 h0 = *(__half2*)&ph[0];
                __half2 h1 = *(__half2*)&ph[1];
                __half2 h2 = *(__half2*)&ph[2];
                __half2 h3 = *(__half2*)&ph[3];
                pl[0] = pack_h2(sacc[jA][0] - __low2float(h0), sacc[jA][1] - __high2float(h0));
                pl[1] = pack_h2(sacc[jA][2] - __low2float(h1), sacc[jA][3] - __high2float(h1));
                pl[2] = pack_h2(sacc[jB][0] - __low2float(h2), sacc[jB][1] - __high2float(h2));
                pl[3] = pack_h2(sacc[jB][2] - __low2float(h3), sacc[jB][3] - __high2float(h3));
            }
#pragma unroll
            for (int nt2 = 0; nt2 < 4; nt2++) {
                int r = nt2 * 16 + bRowBase;
                uint32_t vc = kt2 * 2 + bCsel;
                uint32_t bv[4];
                ldsm4(bv[0], bv[1], bv[2], bv[3], vbse + swzV(r, vc));
                mma16816h(oacc[2*nt2],   ph[0], ph[1], ph[2], ph[3], bv[0], bv[1]);
                mma16816h(oacc[2*nt2+1], ph[0], ph[1], ph[2], ph[3], bv[2], bv[3]);
                mma16816h(oacc[2*nt2],   pl[0], pl[1], pl[2], pl[3], bv[0], bv[1]);
                mma16816h(oacc[2*nt2+1], pl[0], pl[1], pl[2], pl[3], bv[2], bv[3]);
            }
        }
    }

    const float inv0 = 1.0f / l0r, inv1 = 1.0f / l1r;
    const size_t gr0 = (size_t)(b * SEQ + q0 + row0);
    const size_t gr1 = (size_t)(b * SEQ + q0 + row1);
#pragma unroll
    for (int nt = 0; nt < 8; nt++) {
        int col = h * D_HEAD + nt * 8 + qq * 2;
        float a0 = oacc[nt][0] * inv0, a1 = oacc[nt][1] * inv0;
        float b0f = oacc[nt][2] * inv1, b1f = oacc[nt][3] * inv1;
        uint32_t h0 = pack_h2(a0, a1), h1 = pack_h2(b0f, b1f);
        __half2 hh0 = *(__half2*)&h0, hh1 = *(__half2*)&h1;
        uint32_t l0 = pack_h2(a0 - __low2float(hh0), a1 - __high2float(hh0));
        uint32_t l1 = pack_h2(b0f - __low2float(hh1), b1f - __high2float(hh1));
        *(uint32_t*)(g_aoh + gr0 * K2 + col)           = h0;
        *(uint32_t*)(g_aoh + gr0 * K2 + D_MODEL + col) = l0;
        *(uint32_t*)(g_aoh + gr1 * K2 + col)           = h1;
        *(uint32_t*)(g_aoh + gr1 * K2 + D_MODEL + col) = l1;
    }
}

// ---------------------------------------------------------------------------
extern "C" void kernel_launch(void* const* d_in, const int* in_sizes, int n_in,
                              void* d_out, int out_size)
{
    const float* x  = (const float*)d_in[0];
    const float* Wq = (const float*)d_in[1];
    const float* Wk = (const float*)d_in[2];
    const float* Wv = (const float*)d_in[3];
    const float* Wo = (const float*)d_in[4];
    float* out = (float*)d_out;

    void *pqkv, *pxh, *paoh, *pwh;
    cudaGetSymbolAddress(&pqkv, g_qkv);
    cudaGetSymbolAddress(&pxh,  g_xh);
    cudaGetSymbolAddress(&paoh, g_aoh);
    cudaGetSymbolAddress(&pwh,  g_wh);

    __half* xh  = (__half*)pxh;
    __half* aoh = (__half*)paoh;
    __half* wh  = (__half*)pwh;

    cudaFuncSetAttribute(gemm_f16,
                         cudaFuncAttributeMaxDynamicSharedMemorySize, G_SMEM);
    cudaFuncSetAttribute(flash_attn_f16,
                         cudaFuncAttributeMaxDynamicSharedMemorySize, A_SMEM);

    const int n4x = M_ROWS * D_MODEL / 4;
    const int n4w = D_MODEL * D_MODEL / 4;
    const size_t WSZ = (size_t)D_MODEL * D_MODEL;

    split2<<<(n4x + 255) / 256, 256>>>(x, xh, n4x);
    convh4<<<dim3((n4w + 255) / 256, 4), 256>>>(Wq, Wk, Wv, Wo, wh, n4w);

    dim3 qkvgrid(K3 / BN, M_ROWS / BM);      // (12, 64)
    gemm_f16<<<qkvgrid, 512, G_SMEM>>>(xh, wh, (float*)pqkv, K3);

    dim3 pgrid(NQT, N_HEADS, B_SZ);
    prep_attn<<<pgrid, 256>>>();

    dim3 fgrid(NQT, N_HEADS, B_SZ);
    flash_attn_f16<<<fgrid, 256, A_SMEM>>>();

    dim3 ogrid(D_MODEL / BN, M_ROWS / BM);   // (4, 64)
    gemm_f16<<<ogrid, 512, G_SMEM>>>(aoh, wh + 3 * WSZ, out, D_MODEL);
}

// round 9
// speedup vs baseline: 1.0856x; 1.0856x over previous
#include <cuda_runtime.h>
#include <cuda_fp16.h>
#include <cstdint>
#include <math.h>

#define D_MODEL 1024
#define N_HEADS 16
#define D_HEAD  64
#define B_SZ    4
#define SEQ     2048
#define M_ROWS  (B_SZ * SEQ)   // 8192
#define K3      (3 * D_MODEL)  // 3072
#define K2      (2 * D_MODEL)  // 2048
#define WROW    D_MODEL
#define NQT     (SEQ / 128)    // 16

// ---------------- scratch (__device__ globals) ------------------------------
__device__ __half g_xh [M_ROWS * K2];                 // x split [hi | lo]
__device__ __half g_aoh[M_ROWS * K2];                 // attn out split [hi | lo]
__device__ __half g_wh [4 * D_MODEL * D_MODEL];       // weights fp16
// Pre-swizzled fp16 tile images (exact smem layout used by attention):
__device__ __half g_Qp [B_SZ * N_HEADS * NQT * 16384];   // [QHI 16K | QLO 16K] bytes
__device__ __half g_KVp[B_SZ * N_HEADS * NQT * 24576];   // [KHI | KLO | VT]

// ---------------- helpers ----------------------------------------------------
__device__ __forceinline__ uint32_t smem_u32(const void* p) {
    uint32_t a;
    asm("{ .reg .u64 t; cvta.to.shared.u64 t, %1; cvt.u32.u64 %0, t; }" : "=r"(a) : "l"(p));
    return a;
}
__device__ __forceinline__ void cp_async16(uint32_t s, const void* g) {
    asm volatile("cp.async.cg.shared.global [%0], [%1], 16;" :: "r"(s), "l"(g));
}
#define CP_COMMIT() asm volatile("cp.async.commit_group;" ::: "memory")
#define CP_WAIT0()  asm volatile("cp.async.wait_group 0;" ::: "memory")
#define CP_WAIT1()  asm volatile("cp.async.wait_group 1;" ::: "memory")

__device__ __forceinline__ void ldsm4(uint32_t& r0, uint32_t& r1, uint32_t& r2, uint32_t& r3,
                                      uint32_t addr) {
    asm volatile("ldmatrix.sync.aligned.m8n8.x4.shared.b16 {%0,%1,%2,%3}, [%4];"
                 : "=r"(r0), "=r"(r1), "=r"(r2), "=r"(r3) : "r"(addr));
}
__device__ __forceinline__ void mma16816h(float* c, uint32_t a0, uint32_t a1,
                                          uint32_t a2, uint32_t a3,
                                          uint32_t b0, uint32_t b1) {
    asm volatile("mma.sync.aligned.m16n8k16.row.col.f32.f16.f16.f32 "
                 "{%0,%1,%2,%3}, {%4,%5,%6,%7}, {%8,%9}, {%0,%1,%2,%3};"
                 : "+f"(c[0]), "+f"(c[1]), "+f"(c[2]), "+f"(c[3])
                 : "r"(a0), "r"(a1), "r"(a2), "r"(a3), "r"(b0), "r"(b1));
}
__device__ __forceinline__ uint32_t swz(int row, int c) {          // 64B rows
    return (uint32_t)(row * 64 + ((c ^ ((row >> 1) & 3)) << 4));
}
__device__ __forceinline__ uint32_t swz128(int row, int c) {       // 128B rows
    return (uint32_t)(row * 128 + ((c ^ (row & 7)) << 4));
}
__device__ __forceinline__ uint32_t swzV(int row, int c) {         // 256B rows
    return (uint32_t)(row * 256 + ((c ^ (row & 7)) << 4));
}
__device__ __forceinline__ uint32_t pack_h2(float a, float b) {
    __half2 h = __floats2half2_rn(a, b);
    return *(uint32_t*)&h;
}

// ---------------- fp32 -> fp16 [hi|lo] split (pitch K2) ----------------------
__global__ void split2(const float* __restrict__ src, __half* __restrict__ dst, int n4)
{
    int i = blockIdx.x * 256 + threadIdx.x;
    if (i >= n4) return;
    int r = i >> 8;
    int c = (i & 255) * 4;
    float4 v = ((const float4*)src)[i];
    float f[4] = {v.x, v.y, v.z, v.w};
    ushort hb[4], lb[4];
#pragma unroll
    for (int e = 0; e < 4; e++) {
        __half hh = __float2half_rn(f[e]);
        hb[e] = __half_as_ushort(hh);
        lb[e] = __half_as_ushort(__float2half_rn(f[e] - __half2float(hh)));
    }
    size_t base = (size_t)r * K2 + c;
    *(ushort4*)(dst + base)           = *(ushort4*)hb;
    *(ushort4*)(dst + base + D_MODEL) = *(ushort4*)lb;
}

__global__ void convh4(const float* __restrict__ w0, const float* __restrict__ w1,
                       const float* __restrict__ w2, const float* __restrict__ w3,
                       __half* __restrict__ dst, int n4)
{
    int i = blockIdx.x * 256 + threadIdx.x;
    if (i >= n4) return;
    const float* srcs[4] = {w0, w1, w2, w3};
    const float* src = srcs[blockIdx.y];
    __half* d = dst + (size_t)blockIdx.y * D_MODEL * D_MODEL;
    float4 v = ((const float4*)src)[i];
    ushort hb[4] = {
        __half_as_ushort(__float2half_rn(v.x)),
        __half_as_ushort(__float2half_rn(v.y)),
        __half_as_ushort(__float2half_rn(v.z)),
        __half_as_ushort(__float2half_rn(v.w))};
    *(ushort4*)(d + (size_t)i * 4) = *(ushort4*)hb;
}

// ---------------- fp16 NT GEMM core (round-7 proven config) ------------------
#define BM 128
#define BN 128
#define BKT 32
#define STAGES 3
#define STAGE_BYTES 16384
#define G_SMEM (STAGES * STAGE_BYTES)    // 48 KB -> 2 CTAs/SM
#define NKT (K2 / BKT)                   // 64

// Mainloop shared by both GEMMs (computes acc for this thread's tile).
__device__ __forceinline__ void gemm_mainloop(
    const __half* __restrict__ A, const __half* __restrict__ B,
    char* sm, float acc[2][8][4], int m0, int n0)
{
    const uint32_t sbase = smem_u32(sm);
    const int tid  = threadIdx.x;
    const int lane = tid & 31;
    const int wid  = tid >> 5;
    const int wm   = wid & 3;
    const int wn   = wid >> 2;

    const int lr0 = tid >> 2, lc0 = tid & 3;
    const int lr1 = (tid + 256) >> 2, lc1 = (tid + 256) & 3;

    const __half* Ag  = A + (size_t)(m0 + lr0) * K2 + lc0 * 8;
    const __half* Ag1 = A + (size_t)(m0 + lr1) * K2 + lc1 * 8;
    const __half* Bg  = B + (size_t)(n0 + lr0) * WROW + lc0 * 8;
    const __half* Bg1 = B + (size_t)(n0 + lr1) * WROW + lc1 * 8;
    const uint32_t sA0 = swz(lr0, lc0), sA1 = swz(lr1, lc1);

#pragma unroll
    for (int i = 0; i < 2; i++)
#pragma unroll
        for (int j = 0; j < 8; j++)
#pragma unroll
            for (int q = 0; q < 4; q++) acc[i][j][q] = 0.f;

#pragma unroll
    for (int s = 0; s < STAGES - 1; s++) {
        uint32_t st = sbase + s * STAGE_BYTES;
        int ko = s * BKT;
        cp_async16(st + sA0,        Ag  + ko);
        cp_async16(st + sA1,        Ag1 + ko);
        cp_async16(st + 8192 + sA0, Bg  + (ko & 1023));
        cp_async16(st + 8192 + sA1, Bg1 + (ko & 1023));
        CP_COMMIT();
    }

    const int aRow = wm * 32 + (lane & 15);
    const int aCsel = lane >> 4;
    const int bRow = wn * 64 + (lane & 7) + ((lane >> 4) << 3);
    const int bCsel = (lane >> 3) & 1;

    for (int kt = 0; kt < NKT; kt++) {
        CP_WAIT1();
        __syncthreads();

        if (kt + STAGES - 1 < NKT) {
            int s = (kt + STAGES - 1) % STAGES;
            int ko = (kt + STAGES - 1) * BKT;
            uint32_t st = sbase + s * STAGE_BYTES;
            cp_async16(st + sA0,        Ag  + ko);
            cp_async16(st + sA1,        Ag1 + ko);
            cp_async16(st + 8192 + sA0, Bg  + (ko & 1023));
            cp_async16(st + 8192 + sA1, Bg1 + (ko & 1023));
        }
        CP_COMMIT();

        const uint32_t stA = sbase + (kt % STAGES) * STAGE_BYTES;
        const uint32_t stB = stA + 8192;

#pragma unroll
        for (int k16 = 0; k16 < 2; k16++) {
            const int kc = k16 * 2;
            uint32_t af[2][4];
#pragma unroll
            for (int i = 0; i < 2; i++) {
                int r = aRow + i * 16;
                ldsm4(af[i][0], af[i][1], af[i][2], af[i][3],
                      stA + swz(r, kc + aCsel));
            }
            uint32_t bf[4][4];
#pragma unroll
            for (int j = 0; j < 4; j++) {
                int r = bRow + j * 16;
                ldsm4(bf[j][0], bf[j][1], bf[j][2], bf[j][3],
                      stB + swz(r, kc + bCsel));
            }
#pragma unroll
            for (int i = 0; i < 2; i++)
#pragma unroll
                for (int j = 0; j < 4; j++) {
                    mma16816h(acc[i][2*j+0], af[i][0], af[i][1], af[i][2], af[i][3],
                              bf[j][0], bf[j][1]);
                    mma16816h(acc[i][2*j+1], af[i][0], af[i][1], af[i][2], af[i][3],
                              bf[j][2], bf[j][3]);
                }
        }
    }
}

// Generic GEMM with fp32 output (used for the O projection).
__global__ __launch_bounds__(256, 2)
void gemm_f16(const __half* __restrict__ A, const __half* __restrict__ B,
              float* __restrict__ C, int cpitch)
{
    extern __shared__ __align__(128) char sm[];
    const int m0 = blockIdx.y * BM;
    const int n0 = blockIdx.x * BN;
    float acc[2][8][4];
    gemm_mainloop(A, B, sm, acc, m0, n0);

    const int lane = threadIdx.x & 31;
    const int wid  = threadIdx.x >> 5;
    const int wm = wid & 3, wn = wid >> 2;
    const int gid = lane >> 2, q = lane & 3;
#pragma unroll
    for (int i = 0; i < 2; i++) {
        int r0 = m0 + wm * 32 + i * 16 + gid;
#pragma unroll
        for (int j = 0; j < 8; j++) {
            int col = n0 + wn * 64 + j * 8 + q * 2;
            *(float2*)(C + (size_t)r0 * cpitch + col) =
                make_float2(acc[i][j][0], acc[i][j][1]);
            *(float2*)(C + (size_t)(r0 + 8) * cpitch + col) =
                make_float2(acc[i][j][2], acc[i][j][3]);
        }
    }
}

// QKV GEMM with fused prep epilogue: writes pre-swizzled fp16 tile images.
__global__ __launch_bounds__(256, 2)
void gemm_qkv(const __half* __restrict__ A, const __half* __restrict__ B)
{
    extern __shared__ __align__(128) char sm[];
    const int m0 = blockIdx.y * BM;
    const int n0 = blockIdx.x * BN;
    float acc[2][8][4];
    gemm_mainloop(A, B, sm, acc, m0, n0);

    const int lane = threadIdx.x & 31;
    const int wid  = threadIdx.x >> 5;
    const int wm = wid & 3, wn = wid >> 2;
    const int gid = lane >> 2, q = lane & 3;

    const int bb = m0 >> 11;            // batch
    const int t  = (m0 & 2047) >> 7;    // q-tile within batch
    const int region = n0 >> 10;        // 0=Q, 1=K, 2=V
    const int nloc = n0 & 1023;

#pragma unroll
    for (int i = 0; i < 2; i++) {
        const int lrow0 = wm * 32 + i * 16 + gid;   // local token row
        const int lrow1 = lrow0 + 8;
#pragma unroll
        for (int j = 0; j < 8; j++) {
            const int c128 = wn * 64 + j * 8 + q * 2;
            const int n = nloc + c128;
            const int h = n >> 6;
            const int d = n & 63;
            const size_t bh = (size_t)(bb * N_HEADS + h) * NQT + t;

            if (region == 0) {
                // Q: scale 1/8, hi/lo split, swz128 image
                char* qd = (char*)(g_Qp + bh * 16384);
                uint32_t o0 = swz128(lrow0, d >> 3) + (d & 7) * 2;
                uint32_t o1 = swz128(lrow1, d >> 3) + (d & 7) * 2;
                float a0 = acc[i][j][0] * 0.125f, a1 = acc[i][j][1] * 0.125f;
                float b0 = acc[i][j][2] * 0.125f, b1 = acc[i][j][3] * 0.125f;
                uint32_t h0 = pack_h2(a0, a1), h1 = pack_h2(b0, b1);
                __half2 hh0 = *(__half2*)&h0, hh1 = *(__half2*)&h1;
                uint32_t l0 = pack_h2(a0 - __low2float(hh0), a1 - __high2float(hh0));
                uint32_t l1 = pack_h2(b0 - __low2float(hh1), b1 - __high2float(hh1));
                *(uint32_t*)(qd + o0)         = h0;
                *(uint32_t*)(qd + 16384 + o0) = l0;
                *(uint32_t*)(qd + o1)         = h1;
                *(uint32_t*)(qd + 16384 + o1) = l1;
            } else if (region == 1) {
                // K: hi/lo split, swz128 image
                char* kd = (char*)(g_KVp + bh * 24576);
                uint32_t o0 = swz128(lrow0, d >> 3) + (d & 7) * 2;
                uint32_t o1 = swz128(lrow1, d >> 3) + (d & 7) * 2;
                float a0 = acc[i][j][0], a1 = acc[i][j][1];
                float b0 = acc[i][j][2], b1 = acc[i][j][3];
                uint32_t h0 = pack_h2(a0, a1), h1 = pack_h2(b0, b1);
                __half2 hh0 = *(__half2*)&h0, hh1 = *(__half2*)&h1;
                uint32_t l0 = pack_h2(a0 - __low2float(hh0), a1 - __high2float(hh0));
                uint32_t l1 = pack_h2(b0 - __low2float(hh1), b1 - __high2float(hh1));
                *(uint32_t*)(kd + o0)         = h0;
                *(uint32_t*)(kd + 16384 + o0) = l0;
                *(uint32_t*)(kd + o1)         = h1;
                *(uint32_t*)(kd + 16384 + o1) = l1;
            } else {
                // V: single fp16, transposed image (row=d, within-row token)
                char* vd = (char*)(g_KVp + bh * 24576) + 32768;
                uint32_t oa0 = swzV(d,     lrow0 >> 3) + (lrow0 & 7) * 2;
                uint32_t oa1 = swzV(d + 1, lrow0 >> 3) + (lrow0 & 7) * 2;
                uint32_t ob0 = swzV(d,     lrow1 >> 3) + (lrow1 & 7) * 2;
                uint32_t ob1 = swzV(d + 1, lrow1 >> 3) + (lrow1 & 7) * 2;
                *(ushort*)(vd + oa0) = __half_as_ushort(__float2half_rn(acc[i][j][0]));
                *(ushort*)(vd + oa1) = __half_as_ushort(__float2half_rn(acc[i][j][1]));
                *(ushort*)(vd + ob0) = __half_as_ushort(__float2half_rn(acc[i][j][2]));
                *(ushort*)(vd + ob1) = __half_as_ushort(__float2half_rn(acc[i][j][3]));
            }
        }
    }
}

// ---------------------------------------------------------------------------
// Flash attention (round-7 proven): cp.async + ldsm + HMMA, K/V double-buffer
// ---------------------------------------------------------------------------
#define SM_Q   0
#define SM_ST  32768
#define STG    49152
#define A_SMEM (32768 + 2 * 49152)

__global__ __launch_bounds__(256, 1)
void flash_attn_f16()
{
    extern __shared__ __align__(128) char smc[];
    const uint32_t sb = smem_u32(smc);
    const int tid  = threadIdx.x;
    const int lane = tid & 31;
    const int wid  = tid >> 5;
    const int gid  = lane >> 2;
    const int qq   = lane & 3;
    const int qt = gridDim.x - 1 - blockIdx.x;
    const int h  = blockIdx.y;
    const int b  = blockIdx.z;
    const int q0 = qt * 128;
    const size_t bhbase = (size_t)(b * N_HEADS + h) * NQT;

    {
        const char* qs = (const char*)(g_Qp + (bhbase + qt) * 16384);
#pragma unroll
        for (int i = 0; i < 8; i++) {
            uint32_t off = (tid + i * 256) * 16;
            cp_async16(sb + SM_Q + off, qs + off);
        }
        const char* kvs = (const char*)(g_KVp + bhbase * 24576);
#pragma unroll
        for (int i = 0; i < 12; i++) {
            uint32_t off = (tid + i * 256) * 16;
            cp_async16(sb + SM_ST + off, kvs + off);
        }
        CP_COMMIT();
    }
    CP_WAIT0();
    __syncthreads();

    const int aRow = wid * 16 + (lane & 15);
    const int aCsel = lane >> 4;
    uint32_t qh[4][4], ql[4][4];
#pragma unroll
    for (int kt2 = 0; kt2 < 4; kt2++) {
        ldsm4(qh[kt2][0], qh[kt2][1], qh[kt2][2], qh[kt2][3],
              sb + SM_Q + swz128(aRow, kt2 * 2 + aCsel));
        ldsm4(ql[kt2][0], ql[kt2][1], ql[kt2][2], ql[kt2][3],
              sb + SM_Q + 16384 + swz128(aRow, kt2 * 2 + aCsel));
    }

    float m0r = -1e30f, m1r = -1e30f, l0r = 0.f, l1r = 0.f;
    float oacc[8][4];
#pragma unroll
    for (int j = 0; j < 8; j++)
#pragma unroll
        for (int q2 = 0; q2 < 4; q2++) oacc[j][q2] = 0.f;

    const int bRowBase = (lane & 7) + ((lane >> 4) << 3);
    const int bCsel = (lane >> 3) & 1;
    const int row0 = wid * 16 + gid;
    const int row1 = row0 + 8;

    for (int t = 0; t <= qt; t++) {
        if (t > 0) {
            CP_WAIT0();
            __syncthreads();
        }
        if (t < qt) {
            const char* kvs = (const char*)(g_KVp + (bhbase + t + 1) * 24576);
            uint32_t dst = sb + SM_ST + ((t + 1) & 1) * STG;
#pragma unroll
            for (int i = 0; i < 12; i++) {
                uint32_t off = (tid + i * 256) * 16;
                cp_async16(dst + off, kvs + off);
            }
            CP_COMMIT();
        }

        const uint32_t kb = sb + SM_ST + (t & 1) * STG;
        const uint32_t lb = kb + 16384;
        const uint32_t vbse = kb + 32768;

        float sacc[16][4];
#pragma unroll
        for (int j = 0; j < 16; j++)
#pragma unroll
            for (int q2 = 0; q2 < 4; q2++) sacc[j][q2] = 0.f;

#pragma unroll
        for (int kt2 = 0; kt2 < 4; kt2++) {
#pragma unroll
            for (int jt2 = 0; jt2 < 8; jt2++) {
                int r = jt2 * 16 + bRowBase;
                uint32_t kc = kt2 * 2 + bCsel;
                uint32_t bh4[4], bl4[4];
                ldsm4(bh4[0], bh4[1], bh4[2], bh4[3], kb + swz128(r, kc));
                ldsm4(bl4[0], bl4[1], bl4[2], bl4[3], lb + swz128(r, kc));
                mma16816h(sacc[2*jt2],   qh[kt2][0], qh[kt2][1], qh[kt2][2], qh[kt2][3], bh4[0], bh4[1]);
                mma16816h(sacc[2*jt2+1], qh[kt2][0], qh[kt2][1], qh[kt2][2], qh[kt2][3], bh4[2], bh4[3]);
                mma16816h(sacc[2*jt2],   ql[kt2][0], ql[kt2][1], ql[kt2][2], ql[kt2][3], bh4[0], bh4[1]);
                mma16816h(sacc[2*jt2+1], ql[kt2][0], ql[kt2][1], ql[kt2][2], ql[kt2][3], bh4[2], bh4[3]);
                mma16816h(sacc[2*jt2],   qh[kt2][0], qh[kt2][1], qh[kt2][2], qh[kt2][3], bl4[0], bl4[1]);
                mma16816h(sacc[2*jt2+1], qh[kt2][0], qh[kt2][1], qh[kt2][2], qh[kt2][3], bl4[2], bl4[3]);
            }
        }

        if (t == qt) {
#pragma unroll
            for (int j = 0; j < 16; j++) {
                int c0 = j * 8 + qq * 2;
                if (c0 > row0)     sacc[j][0] = -1e30f;
                if (c0 + 1 > row0) sacc[j][1] = -1e30f;
                if (c0 > row1)     sacc[j][2] = -1e30f;
                if (c0 + 1 > row1) sacc[j][3] = -1e30f;
            }
        }

        float mx0 = -1e30f, mx1 = -1e30f;
#pragma unroll
        for (int j = 0; j < 16; j++) {
            mx0 = fmaxf(mx0, fmaxf(sacc[j][0], sacc[j][1]));
            mx1 = fmaxf(mx1, fmaxf(sacc[j][2], sacc[j][3]));
        }
        mx0 = fmaxf(mx0, __shfl_xor_sync(0xffffffffu, mx0, 1));
        mx0 = fmaxf(mx0, __shfl_xor_sync(0xffffffffu, mx0, 2));
        mx1 = fmaxf(mx1, __shfl_xor_sync(0xffffffffu, mx1, 1));
        mx1 = fmaxf(mx1, __shfl_xor_sync(0xffffffffu, mx1, 2));

        float mn0 = fmaxf(m0r, mx0), mn1 = fmaxf(m1r, mx1);
        float cr0 = __expf(m0r - mn0), cr1 = __expf(m1r - mn1);
        float sum0 = 0.f, sum1 = 0.f;
#pragma unroll
        for (int j = 0; j < 16; j++) {
            sacc[j][0] = __expf(sacc[j][0] - mn0);
            sacc[j][1] = __expf(sacc[j][1] - mn0);
            sacc[j][2] = __expf(sacc[j][2] - mn1);
            sacc[j][3] = __expf(sacc[j][3] - mn1);
            sum0 += sacc[j][0] + sacc[j][1];
            sum1 += sacc[j][2] + sacc[j][3];
        }
        sum0 += __shfl_xor_sync(0xffffffffu, sum0, 1);
        sum0 += __shfl_xor_sync(0xffffffffu, sum0, 2);
        sum1 += __shfl_xor_sync(0xffffffffu, sum1, 1);
        sum1 += __shfl_xor_sync(0xffffffffu, sum1, 2);

        l0r = l0r * cr0 + sum0;  m0r = mn0;
        l1r = l1r * cr1 + sum1;  m1r = mn1;
#pragma unroll
        for (int j = 0; j < 8; j++) {
            oacc[j][0] *= cr0; oacc[j][1] *= cr0;
            oacc[j][2] *= cr1; oacc[j][3] *= cr1;
        }

#pragma unroll
        for (int kt2 = 0; kt2 < 8; kt2++) {
            const int jA = 2 * kt2, jB = 2 * kt2 + 1;
            uint32_t ph[4], pl[4];
            ph[0] = pack_h2(sacc[jA][0], sacc[jA][1]);
            ph[1] = pack_h2(sacc[jA][2], sacc[jA][3]);
            ph[2] = pack_h2(sacc[jB][0], sacc[jB][1]);
            ph[3] = pack_h2(sacc[jB][2], sacc[jB][3]);
            {
                __half2 h0 = *(__half2*)&ph[0];
                __half2 h1 = *(__half2*)&ph[1];
                __half2 h2 = *(__half2*)&ph[2];
                __half2 h3 = *(__half2*)&ph[3];
                pl[0] = pack_h2(sacc[jA][0] - __low2float(h0), sacc[jA][1] - __high2float(h0));
                pl[1] = pack_h2(sacc[jA][2] - __low2float(h1), sacc[jA][3] - __high2float(h1));
                pl[2] = pack_h2(sacc[jB][0] - __low2float(h2), sacc[jB][1] - __high2float(h2));
                pl[3] = pack_h2(sacc[jB][2] - __low2float(h3), sacc[jB][3] - __high2float(h3));
            }
#pragma unroll
            for (int nt2 = 0; nt2 < 4; nt2++) {
                int r = nt2 * 16 + bRowBase;
                uint32_t vc = kt2 * 2 + bCsel;
                uint32_t bv[4];
                ldsm4(bv[0], bv[1], bv[2], bv[3], vbse + swzV(r, vc));
                mma16816h(oacc[2*nt2],   ph[0], ph[1], ph[2], ph[3], bv[0], bv[1]);
                mma16816h(oacc[2*nt2+1], ph[0], ph[1], ph[2], ph[3], bv[2], bv[3]);
                mma16816h(oacc[2*nt2],   pl[0], pl[1], pl[2], pl[3], bv[0], bv[1]);
                mma16816h(oacc[2*nt2+1], pl[0], pl[1], pl[2], pl[3], bv[2], bv[3]);
            }
        }
    }

    const float inv0 = 1.0f / l0r, inv1 = 1.0f / l1r;
    const size_t gr0 = (size_t)(b * SEQ + q0 + row0);
    const size_t gr1 = (size_t)(b * SEQ + q0 + row1);
#pragma unroll
    for (int nt = 0; nt < 8; nt++) {
        int col = h * D_HEAD + nt * 8 + qq * 2;
        float a0 = oacc[nt][0] * inv0, a1 = oacc[nt][1] * inv0;
        float b0f = oacc[nt][2] * inv1, b1f = oacc[nt][3] * inv1;
        uint32_t h0 = pack_h2(a0, a1), h1 = pack_h2(b0f, b1f);
        __half2 hh0 = *(__half2*)&h0, hh1 = *(__half2*)&h1;
        uint32_t l0 = pack_h2(a0 - __low2float(hh0), a1 - __high2float(hh0));
        uint32_t l1 = pack_h2(b0f - __low2float(hh1), b1f - __high2float(hh1));
        *(uint32_t*)(g_aoh + gr0 * K2 + col)           = h0;
        *(uint32_t*)(g_aoh + gr0 * K2 + D_MODEL + col) = l0;
        *(uint32_t*)(g_aoh + gr1 * K2 + col)           = h1;
        *(uint32_t*)(g_aoh + gr1 * K2 + D_MODEL + col) = l1;
    }
}

// ---------------------------------------------------------------------------
extern "C" void kernel_launch(void* const* d_in, const int* in_sizes, int n_in,
                              void* d_out, int out_size)
{
    const float* x  = (const float*)d_in[0];
    const float* Wq = (const float*)d_in[1];
    const float* Wk = (const float*)d_in[2];
    const float* Wv = (const float*)d_in[3];
    const float* Wo = (const float*)d_in[4];
    float* out = (float*)d_out;

    void *pxh, *paoh, *pwh;
    cudaGetSymbolAddress(&pxh,  g_xh);
    cudaGetSymbolAddress(&paoh, g_aoh);
    cudaGetSymbolAddress(&pwh,  g_wh);

    __half* xh  = (__half*)pxh;
    __half* aoh = (__half*)paoh;
    __half* wh  = (__half*)pwh;

    cudaFuncSetAttribute(gemm_f16,
                         cudaFuncAttributeMaxDynamicSharedMemorySize, G_SMEM);
    cudaFuncSetAttribute(gemm_qkv,
                         cudaFuncAttributeMaxDynamicSharedMemorySize, G_SMEM);
    cudaFuncSetAttribute(flash_attn_f16,
                         cudaFuncAttributeMaxDynamicSharedMemorySize, A_SMEM);

    const int n4x = M_ROWS * D_MODEL / 4;
    const int n4w = D_MODEL * D_MODEL / 4;
    const size_t WSZ = (size_t)D_MODEL * D_MODEL;

    split2<<<(n4x + 255) / 256, 256>>>(x, xh, n4x);
    convh4<<<dim3((n4w + 255) / 256, 4), 256>>>(Wq, Wk, Wv, Wo, wh, n4w);

    // QKV GEMM with fused prep epilogue
    dim3 qkvgrid(K3 / BN, M_ROWS / BM);      // (24, 64)
    gemm_qkv<<<qkvgrid, 256, G_SMEM>>>(xh, wh);

    dim3 fgrid(NQT, N_HEADS, B_SZ);          // (16, 16, 4)
    flash_attn_f16<<<fgrid, 256, A_SMEM>>>();

    dim3 ogrid(D_MODEL / BN, M_ROWS / BM);   // (8, 64)
    gemm_f16<<<ogrid, 256, G_SMEM>>>(aoh, wh + 3 * WSZ, out, D_MODEL);
}

// round 10
// speedup vs baseline: 1.1647x; 1.0729x over previous
#include <cuda_runtime.h>
#include <cuda_fp16.h>
#include <cstdint>
#include <math.h>

#define D_MODEL 1024
#define N_HEADS 16
#define D_HEAD  64
#define B_SZ    4
#define SEQ     2048
#define M_ROWS  (B_SZ * SEQ)   // 8192
#define K3      (3 * D_MODEL)  // 3072
#define K2      (2 * D_MODEL)  // 2048
#define WROW    D_MODEL
#define NQT     (SEQ / 128)    // 16
#define N4X     (M_ROWS * D_MODEL / 4)     // 2097152
#define N4W     (D_MODEL * D_MODEL / 4)    // 262144 = 2^18

// ---------------- scratch (__device__ globals) ------------------------------
__device__ __half g_xh [M_ROWS * K2];                 // x split [hi | lo]
__device__ __half g_aoh[M_ROWS * K2];                 // attn out split [hi | lo]
__device__ __half g_wh [4 * D_MODEL * D_MODEL];       // weights fp16
__device__ __half g_Qp [B_SZ * N_HEADS * NQT * 16384];   // [QHI | QLO] swizzled
__device__ __half g_KVp[B_SZ * N_HEADS * NQT * 24576];   // [KHI | KLO | VT]

// ---------------- helpers ----------------------------------------------------
__device__ __forceinline__ uint32_t smem_u32(const void* p) {
    uint32_t a;
    asm("{ .reg .u64 t; cvta.to.shared.u64 t, %1; cvt.u32.u64 %0, t; }" : "=r"(a) : "l"(p));
    return a;
}
__device__ __forceinline__ void cp_async16(uint32_t s, const void* g) {
    asm volatile("cp.async.cg.shared.global [%0], [%1], 16;" :: "r"(s), "l"(g));
}
#define CP_COMMIT() asm volatile("cp.async.commit_group;" ::: "memory")
#define CP_WAIT0()  asm volatile("cp.async.wait_group 0;" ::: "memory")
#define CP_WAIT1()  asm volatile("cp.async.wait_group 1;" ::: "memory")

__device__ __forceinline__ void ldsm4(uint32_t& r0, uint32_t& r1, uint32_t& r2, uint32_t& r3,
                                      uint32_t addr) {
    asm volatile("ldmatrix.sync.aligned.m8n8.x4.shared.b16 {%0,%1,%2,%3}, [%4];"
                 : "=r"(r0), "=r"(r1), "=r"(r2), "=r"(r3) : "r"(addr));
}
__device__ __forceinline__ void mma16816h(float* c, uint32_t a0, uint32_t a1,
                                          uint32_t a2, uint32_t a3,
                                          uint32_t b0, uint32_t b1) {
    asm volatile("mma.sync.aligned.m16n8k16.row.col.f32.f16.f16.f32 "
                 "{%0,%1,%2,%3}, {%4,%5,%6,%7}, {%8,%9}, {%0,%1,%2,%3};"
                 : "+f"(c[0]), "+f"(c[1]), "+f"(c[2]), "+f"(c[3])
                 : "r"(a0), "r"(a1), "r"(a2), "r"(a3), "r"(b0), "r"(b1));
}
__device__ __forceinline__ uint32_t swz128(int row, int c) {       // 128B rows
    return (uint32_t)(row * 128 + ((c ^ (row & 7)) << 4));
}
__device__ __forceinline__ uint32_t swzV(int row, int c) {         // 256B rows
    return (uint32_t)(row * 256 + ((c ^ (row & 7)) << 4));
}
__device__ __forceinline__ uint32_t pack_h2(float a, float b) {
    __half2 h = __floats2half2_rn(a, b);
    return *(uint32_t*)&h;
}
__device__ __forceinline__ float ex2(float x) {
    float y;
    asm("ex2.approx.ftz.f32 %0, %1;" : "=f"(y) : "f"(x));
    return y;
}

// ---------------- fused conversions: x split + 4 weight converts -------------
__global__ void convert_all(const float* __restrict__ x,
                            const float* __restrict__ w0, const float* __restrict__ w1,
                            const float* __restrict__ w2, const float* __restrict__ w3)
{
    int i = blockIdx.x * 256 + threadIdx.x;
    if (i < N4X) {
        int r = i >> 8;
        int c = (i & 255) * 4;
        float4 v = ((const float4*)x)[i];
        float f[4] = {v.x, v.y, v.z, v.w};
        ushort hb[4], lb[4];
#pragma unroll
        for (int e = 0; e < 4; e++) {
            __half hh = __float2half_rn(f[e]);
            hb[e] = __half_as_ushort(hh);
            lb[e] = __half_as_ushort(__float2half_rn(f[e] - __half2float(hh)));
        }
        size_t base = (size_t)r * K2 + c;
        *(ushort4*)(g_xh + base)           = *(ushort4*)hb;
        *(ushort4*)(g_xh + base + D_MODEL) = *(ushort4*)lb;
    } else {
        int j = i - N4X;
        int w = j >> 18;                 // N4W = 2^18
        int idx = j & (N4W - 1);
        const float* src = (w == 0) ? w0 : (w == 1) ? w1 : (w == 2) ? w2 : w3;
        float4 v = ((const float4*)src)[idx];
        ushort hb[4] = {
            __half_as_ushort(__float2half_rn(v.x)),
            __half_as_ushort(__float2half_rn(v.y)),
            __half_as_ushort(__float2half_rn(v.z)),
            __half_as_ushort(__float2half_rn(v.w))};
        *(ushort4*)(g_wh + (size_t)w * D_MODEL * D_MODEL + (size_t)idx * 4) = *(ushort4*)hb;
    }
}

// ---------------- fp16 NT GEMM core: BKT=64, 3 stages, 2 CTAs/SM -------------
#define BM 128
#define BN 128
#define BKT 64
#define STAGES 3
#define STG_HALF 16384                   // A or B half-stage: 128 rows x 128B
#define STAGE_BYTES 32768
#define G_SMEM (STAGES * STAGE_BYTES)    // 96 KB -> 2 CTAs/SM (192 KB)
#define NKT (K2 / BKT)                   // 32

__device__ __forceinline__ void gemm_mainloop(
    const __half* __restrict__ A, const __half* __restrict__ B,
    char* sm, float acc[2][8][4], int m0, int n0)
{
    const uint32_t sbase = smem_u32(sm);
    const int tid  = threadIdx.x;
    const int lane = tid & 31;
    const int wid  = tid >> 5;
    const int wm   = wid & 3;
    const int wn   = wid >> 2;

    // loads: 1024 chunks of 16B per operand per stage; 4 per thread
    const int lr = tid >> 3, lc = tid & 7;          // base: rows step 32 per it
    const __half* Ag = A + (size_t)(m0 + lr) * K2 + lc * 8;
    const __half* Bg = B + (size_t)(n0 + lr) * WROW + lc * 8;

#pragma unroll
    for (int i = 0; i < 2; i++)
#pragma unroll
        for (int j = 0; j < 8; j++)
#pragma unroll
            for (int q = 0; q < 4; q++) acc[i][j][q] = 0.f;

#pragma unroll
    for (int s = 0; s < STAGES - 1; s++) {
        uint32_t st = sbase + s * STAGE_BYTES;
        int ko = s * BKT;
#pragma unroll
        for (int it = 0; it < 4; it++) {
            int r = lr + it * 32;
            uint32_t so = swz128(r, lc);
            cp_async16(st + so,            Ag + (size_t)(it * 32) * K2 + ko);
            cp_async16(st + STG_HALF + so, Bg + (size_t)(it * 32) * WROW + (ko & 1023));
        }
        CP_COMMIT();
    }

    const int aRow = wm * 32 + (lane & 15);
    const int aCsel = lane >> 4;
    const int bRow = wn * 64 + (lane & 7) + ((lane >> 4) << 3);
    const int bCsel = (lane >> 3) & 1;

    for (int kt = 0; kt < NKT; kt++) {
        CP_WAIT1();
        __syncthreads();

        if (kt + STAGES - 1 < NKT) {
            int s = (kt + STAGES - 1) % STAGES;
            int ko = (kt + STAGES - 1) * BKT;
            uint32_t st = sbase + s * STAGE_BYTES;
#pragma unroll
            for (int it = 0; it < 4; it++) {
                int r = lr + it * 32;
                uint32_t so = swz128(r, lc);
                cp_async16(st + so,            Ag + (size_t)(it * 32) * K2 + ko);
                cp_async16(st + STG_HALF + so, Bg + (size_t)(it * 32) * WROW + (ko & 1023));
            }
        }
        CP_COMMIT();

        const uint32_t stA = sbase + (kt % STAGES) * STAGE_BYTES;
        const uint32_t stB = stA + STG_HALF;

#pragma unroll
        for (int k16 = 0; k16 < 4; k16++) {
            const int kc = k16 * 2;
            uint32_t af[2][4];
#pragma unroll
            for (int i = 0; i < 2; i++) {
                int r = aRow + i * 16;
                ldsm4(af[i][0], af[i][1], af[i][2], af[i][3],
                      stA + swz128(r, kc + aCsel));
            }
            uint32_t bf[4][4];
#pragma unroll
            for (int j = 0; j < 4; j++) {
                int r = bRow + j * 16;
                ldsm4(bf[j][0], bf[j][1], bf[j][2], bf[j][3],
                      stB + swz128(r, kc + bCsel));
            }
#pragma unroll
            for (int i = 0; i < 2; i++)
#pragma unroll
                for (int j = 0; j < 4; j++) {
                    mma16816h(acc[i][2*j+0], af[i][0], af[i][1], af[i][2], af[i][3],
                              bf[j][0], bf[j][1]);
                    mma16816h(acc[i][2*j+1], af[i][0], af[i][1], af[i][2], af[i][3],
                              bf[j][2], bf[j][3]);
                }
        }
    }
}

// Generic GEMM with fp32 output (O projection).
__global__ __launch_bounds__(256, 2)
void gemm_f16(const __half* __restrict__ A, const __half* __restrict__ B,
              float* __restrict__ C, int cpitch)
{
    extern __shared__ __align__(128) char sm[];
    const int m0 = blockIdx.y * BM;
    const int n0 = blockIdx.x * BN;
    float acc[2][8][4];
    gemm_mainloop(A, B, sm, acc, m0, n0);

    const int lane = threadIdx.x & 31;
    const int wid  = threadIdx.x >> 5;
    const int wm = wid & 3, wn = wid >> 2;
    const int gid = lane >> 2, q = lane & 3;
#pragma unroll
    for (int i = 0; i < 2; i++) {
        int r0 = m0 + wm * 32 + i * 16 + gid;
#pragma unroll
        for (int j = 0; j < 8; j++) {
            int col = n0 + wn * 64 + j * 8 + q * 2;
            *(float2*)(C + (size_t)r0 * cpitch + col) =
                make_float2(acc[i][j][0], acc[i][j][1]);
            *(float2*)(C + (size_t)(r0 + 8) * cpitch + col) =
                make_float2(acc[i][j][2], acc[i][j][3]);
        }
    }
}

// QKV GEMM with fused prep epilogue (Q pre-scaled by 0.125*log2e for exp2 softmax).
__global__ __launch_bounds__(256, 2)
void gemm_qkv(const __half* __restrict__ A, const __half* __restrict__ B)
{
    extern __shared__ __align__(128) char sm[];
    const int m0 = blockIdx.y * BM;
    const int n0 = blockIdx.x * BN;
    float acc[2][8][4];
    gemm_mainloop(A, B, sm, acc, m0, n0);

    const int lane = threadIdx.x & 31;
    const int wid  = threadIdx.x >> 5;
    const int wm = wid & 3, wn = wid >> 2;
    const int gid = lane >> 2, q = lane & 3;

    const int bb = m0 >> 11;
    const int t  = (m0 & 2047) >> 7;
    const int region = n0 >> 10;
    const int nloc = n0 & 1023;
    const float QSCALE = 0.125f * 1.4426950408889634f;   // 1/sqrt(dh) * log2(e)

#pragma unroll
    for (int i = 0; i < 2; i++) {
        const int lrow0 = wm * 32 + i * 16 + gid;
        const int lrow1 = lrow0 + 8;
#pragma unroll
        for (int j = 0; j < 8; j++) {
            const int c128 = wn * 64 + j * 8 + q * 2;
            const int n = nloc + c128;
            const int h = n >> 6;
            const int d = n & 63;
            const size_t bh = (size_t)(bb * N_HEADS + h) * NQT + t;

            if (region == 0) {
                char* qd = (char*)(g_Qp + bh * 16384);
                uint32_t o0 = swz128(lrow0, d >> 3) + (d & 7) * 2;
                uint32_t o1 = swz128(lrow1, d >> 3) + (d & 7) * 2;
                float a0 = acc[i][j][0] * QSCALE, a1 = acc[i][j][1] * QSCALE;
                float b0 = acc[i][j][2] * QSCALE, b1 = acc[i][j][3] * QSCALE;
                uint32_t h0 = pack_h2(a0, a1), h1 = pack_h2(b0, b1);
                __half2 hh0 = *(__half2*)&h0, hh1 = *(__half2*)&h1;
                uint32_t l0 = pack_h2(a0 - __low2float(hh0), a1 - __high2float(hh0));
                uint32_t l1 = pack_h2(b0 - __low2float(hh1), b1 - __high2float(hh1));
                *(uint32_t*)(qd + o0)         = h0;
                *(uint32_t*)(qd + 16384 + o0) = l0;
                *(uint32_t*)(qd + o1)         = h1;
                *(uint32_t*)(qd + 16384 + o1) = l1;
            } else if (region == 1) {
                char* kd = (char*)(g_KVp + bh * 24576);
                uint32_t o0 = swz128(lrow0, d >> 3) + (d & 7) * 2;
                uint32_t o1 = swz128(lrow1, d >> 3) + (d & 7) * 2;
                float a0 = acc[i][j][0], a1 = acc[i][j][1];
                float b0 = acc[i][j][2], b1 = acc[i][j][3];
                uint32_t h0 = pack_h2(a0, a1), h1 = pack_h2(b0, b1);
                __half2 hh0 = *(__half2*)&h0, hh1 = *(__half2*)&h1;
                uint32_t l0 = pack_h2(a0 - __low2float(hh0), a1 - __high2float(hh0));
                uint32_t l1 = pack_h2(b0 - __low2float(hh1), b1 - __high2float(hh1));
                *(uint32_t*)(kd + o0)         = h0;
                *(uint32_t*)(kd + 16384 + o0) = l0;
                *(uint32_t*)(kd + o1)         = h1;
                *(uint32_t*)(kd + 16384 + o1) = l1;
            } else {
                char* vd = (char*)(g_KVp + bh * 24576) + 32768;
                uint32_t oa0 = swzV(d,     lrow0 >> 3) + (lrow0 & 7) * 2;
                uint32_t oa1 = swzV(d + 1, lrow0 >> 3) + (lrow0 & 7) * 2;
                uint32_t ob0 = swzV(d,     lrow1 >> 3) + (lrow1 & 7) * 2;
                uint32_t ob1 = swzV(d + 1, lrow1 >> 3) + (lrow1 & 7) * 2;
                *(ushort*)(vd + oa0) = __half_as_ushort(__float2half_rn(acc[i][j][0]));
                *(ushort*)(vd + oa1) = __half_as_ushort(__float2half_rn(acc[i][j][1]));
                *(ushort*)(vd + ob0) = __half_as_ushort(__float2half_rn(acc[i][j][2]));
                *(ushort*)(vd + ob1) = __half_as_ushort(__float2half_rn(acc[i][j][3]));
            }
        }
    }
}

// ---------------------------------------------------------------------------
// Flash attention: cp.async + ldsm + HMMA; exp2-domain softmax.
// ---------------------------------------------------------------------------
#define SM_Q   0
#define SM_ST  32768
#define STG    49152
#define A_SMEM (32768 + 2 * 49152)

__global__ __launch_bounds__(256, 1)
void flash_attn_f16()
{
    extern __shared__ __align__(128) char smc[];
    const uint32_t sb = smem_u32(smc);
    const int tid  = threadIdx.x;
    const int lane = tid & 31;
    const int wid  = tid >> 5;
    const int gid  = lane >> 2;
    const int qq   = lane & 3;
    const int qt = gridDim.x - 1 - blockIdx.x;
    const int h  = blockIdx.y;
    const int b  = blockIdx.z;
    const int q0 = qt * 128;
    const size_t bhbase = (size_t)(b * N_HEADS + h) * NQT;

    {
        const char* qs = (const char*)(g_Qp + (bhbase + qt) * 16384);
#pragma unroll
        for (int i = 0; i < 8; i++) {
            uint32_t off = (tid + i * 256) * 16;
            cp_async16(sb + SM_Q + off, qs + off);
        }
        const char* kvs = (const char*)(g_KVp + bhbase * 24576);
#pragma unroll
        for (int i = 0; i < 12; i++) {
            uint32_t off = (tid + i * 256) * 16;
            cp_async16(sb + SM_ST + off, kvs + off);
        }
        CP_COMMIT();
    }
    CP_WAIT0();
    __syncthreads();

    const int aRow = wid * 16 + (lane & 15);
    const int aCsel = lane >> 4;
    uint32_t qh[4][4], ql[4][4];
#pragma unroll
    for (int kt2 = 0; kt2 < 4; kt2++) {
        ldsm4(qh[kt2][0], qh[kt2][1], qh[kt2][2], qh[kt2][3],
              sb + SM_Q + swz128(aRow, kt2 * 2 + aCsel));
        ldsm4(ql[kt2][0], ql[kt2][1], ql[kt2][2], ql[kt2][3],
              sb + SM_Q + 16384 + swz128(aRow, kt2 * 2 + aCsel));
    }

    float m0r = -1e30f, m1r = -1e30f, l0r = 0.f, l1r = 0.f;
    float oacc[8][4];
#pragma unroll
    for (int j = 0; j < 8; j++)
#pragma unroll
        for (int q2 = 0; q2 < 4; q2++) oacc[j][q2] = 0.f;

    const int bRowBase = (lane & 7) + ((lane >> 4) << 3);
    const int bCsel = (lane >> 3) & 1;
    const int row0 = wid * 16 + gid;
    const int row1 = row0 + 8;

    for (int t = 0; t <= qt; t++) {
        if (t > 0) {
            CP_WAIT0();
            __syncthreads();
        }
        if (t < qt) {
            const char* kvs = (const char*)(g_KVp + (bhbase + t + 1) * 24576);
            uint32_t dst = sb + SM_ST + ((t + 1) & 1) * STG;
#pragma unroll
            for (int i = 0; i < 12; i++) {
                uint32_t off = (tid + i * 256) * 16;
                cp_async16(dst + off, kvs + off);
            }
            CP_COMMIT();
        }

        const uint32_t kb = sb + SM_ST + (t & 1) * STG;
        const uint32_t lb = kb + 16384;
        const uint32_t vbse = kb + 32768;

        float sacc[16][4];
#pragma unroll
        for (int j = 0; j < 16; j++)
#pragma unroll
            for (int q2 = 0; q2 < 4; q2++) sacc[j][q2] = 0.f;

#pragma unroll
        for (int kt2 = 0; kt2 < 4; kt2++) {
#pragma unroll
            for (int jt2 = 0; jt2 < 8; jt2++) {
                int r = jt2 * 16 + bRowBase;
                uint32_t kc = kt2 * 2 + bCsel;
                uint32_t bh4[4], bl4[4];
                ldsm4(bh4[0], bh4[1], bh4[2], bh4[3], kb + swz128(r, kc));
                ldsm4(bl4[0], bl4[1], bl4[2], bl4[3], lb + swz128(r, kc));
                mma16816h(sacc[2*jt2],   qh[kt2][0], qh[kt2][1], qh[kt2][2], qh[kt2][3], bh4[0], bh4[1]);
                mma16816h(sacc[2*jt2+1], qh[kt2][0], qh[kt2][1], qh[kt2][2], qh[kt2][3], bh4[2], bh4[3]);
                mma16816h(sacc[2*jt2],   ql[kt2][0], ql[kt2][1], ql[kt2][2], ql[kt2][3], bh4[0], bh4[1]);
                mma16816h(sacc[2*jt2+1], ql[kt2][0], ql[kt2][1], ql[kt2][2], ql[kt2][3], bh4[2], bh4[3]);
                mma16816h(sacc[2*jt2],   qh[kt2][0], qh[kt2][1], qh[kt2][2], qh[kt2][3], bl4[0], bl4[1]);
                mma16816h(sacc[2*jt2+1], qh[kt2][0], qh[kt2][1], qh[kt2][2], qh[kt2][3], bl4[2], bl4[3]);
            }
        }

        if (t == qt) {
#pragma unroll
            for (int j = 0; j < 16; j++) {
                int c0 = j * 8 + qq * 2;
                if (c0 > row0)     sacc[j][0] = -1e30f;
                if (c0 + 1 > row0) sacc[j][1] = -1e30f;
                if (c0 > row1)     sacc[j][2] = -1e30f;
                if (c0 + 1 > row1) sacc[j][3] = -1e30f;
            }
        }

        float mx0 = -1e30f, mx1 = -1e30f;
#pragma unroll
        for (int j = 0; j < 16; j++) {
            mx0 = fmaxf(mx0, fmaxf(sacc[j][0], sacc[j][1]));
            mx1 = fmaxf(mx1, fmaxf(sacc[j][2], sacc[j][3]));
        }
        mx0 = fmaxf(mx0, __shfl_xor_sync(0xffffffffu, mx0, 1));
        mx0 = fmaxf(mx0, __shfl_xor_sync(0xffffffffu, mx0, 2));
        mx1 = fmaxf(mx1, __shfl_xor_sync(0xffffffffu, mx1, 1));
        mx1 = fmaxf(mx1, __shfl_xor_sync(0xffffffffu, mx1, 2));

        float mn0 = fmaxf(m0r, mx0), mn1 = fmaxf(m1r, mx1);
        float cr0 = ex2(m0r - mn0), cr1 = ex2(m1r - mn1);
        float sum0 = 0.f, sum1 = 0.f;
#pragma unroll
        for (int j = 0; j < 16; j++) {
            sacc[j][0] = ex2(sacc[j][0] - mn0);
            sacc[j][1] = ex2(sacc[j][1] - mn0);
            sacc[j][2] = ex2(sacc[j][2] - mn1);
            sacc[j][3] = ex2(sacc[j][3] - mn1);
            sum0 += sacc[j][0] + sacc[j][1];
            sum1 += sacc[j][2] + sacc[j][3];
        }
        sum0 += __shfl_xor_sync(0xffffffffu, sum0, 1);
        sum0 += __shfl_xor_sync(0xffffffffu, sum0, 2);
        sum1 += __shfl_xor_sync(0xffffffffu, sum1, 1);
        sum1 += __shfl_xor_sync(0xffffffffu, sum1, 2);

        l0r = l0r * cr0 + sum0;  m0r = mn0;
        l1r = l1r * cr1 + sum1;  m1r = mn1;
#pragma unroll
        for (int j = 0; j < 8; j++) {
            oacc[j][0] *= cr0; oacc[j][1] *= cr0;
            oacc[j][2] *= cr1; oacc[j][3] *= cr1;
        }

#pragma unroll
        for (int kt2 = 0; kt2 < 8; kt2++) {
            const int jA = 2 * kt2, jB = 2 * kt2 + 1;
            uint32_t ph[4], pl[4];
            ph[0] = pack_h2(sacc[jA][0], sacc[jA][1]);
            ph[1] = pack_h2(sacc[jA][2], sacc[jA][3]);
            ph[2] = pack_h2(sacc[jB][0], sacc[jB][1]);
            ph[3] = pack_h2(sacc[jB][2], sacc[jB][3]);
            {
                __half2 h0 = *(__half2*)&ph[0];
                __half2 h1 = *(__half2*)&ph[1];
                __half2 h2 = *(__half2*)&ph[2];
                __half2 h3 = *(__half2*)&ph[3];
                pl[0] = pack_h2(sacc[jA][0] - __low2float(h0), sacc[jA][1] - __high2float(h0));
                pl[1] = pack_h2(sacc[jA][2] - __low2float(h1), sacc[jA][3] - __high2float(h1));
                pl[2] = pack_h2(sacc[jB][0] - __low2float(h2), sacc[jB][1] - __high2float(h2));
                pl[3] = pack_h2(sacc[jB][2] - __low2float(h3), sacc[jB][3] - __high2float(h3));
            }
#pragma unroll
            for (int nt2 = 0; nt2 < 4; nt2++) {
                int r = nt2 * 16 + bRowBase;
                uint32_t vc = kt2 * 2 + bCsel;
                uint32_t bv[4];
                ldsm4(bv[0], bv[1], bv[2], bv[3], vbse + swzV(r, vc));
                mma16816h(oacc[2*nt2],   ph[0], ph[1], ph[2], ph[3], bv[0], bv[1]);
                mma16816h(oacc[2*nt2+1], ph[0], ph[1], ph[2], ph[3], bv[2], bv[3]);
                mma16816h(oacc[2*nt2],   pl[0], pl[1], pl[2], pl[3], bv[0], bv[1]);
                mma16816h(oacc[2*nt2+1], pl[0], pl[1], pl[2], pl[3], bv[2], bv[3]);
            }
        }
    }

    const float inv0 = 1.0f / l0r, inv1 = 1.0f / l1r;
    const size_t gr0 = (size_t)(b * SEQ + q0 + row0);
    const size_t gr1 = (size_t)(b * SEQ + q0 + row1);
#pragma unroll
    for (int nt = 0; nt < 8; nt++) {
        int col = h * D_HEAD + nt * 8 + qq * 2;
        float a0 = oacc[nt][0] * inv0, a1 = oacc[nt][1] * inv0;
        float b0f = oacc[nt][2] * inv1, b1f = oacc[nt][3] * inv1;
        uint32_t h0 = pack_h2(a0, a1), h1 = pack_h2(b0f, b1f);
        __half2 hh0 = *(__half2*)&h0, hh1 = *(__half2*)&h1;
        uint32_t l0 = pack_h2(a0 - __low2float(hh0), a1 - __high2float(hh0));
        uint32_t l1 = pack_h2(b0f - __low2float(hh1), b1f - __high2float(hh1));
        *(uint32_t*)(g_aoh + gr0 * K2 + col)           = h0;
        *(uint32_t*)(g_aoh + gr0 * K2 + D_MODEL + col) = l0;
        *(uint32_t*)(g_aoh + gr1 * K2 + col)           = h1;
        *(uint32_t*)(g_aoh + gr1 * K2 + D_MODEL + col) = l1;
    }
}

// ---------------------------------------------------------------------------
extern "C" void kernel_launch(void* const* d_in, const int* in_sizes, int n_in,
                              void* d_out, int out_size)
{
    const float* x  = (const float*)d_in[0];
    const float* Wq = (const float*)d_in[1];
    const float* Wk = (const float*)d_in[2];
    const float* Wv = (const float*)d_in[3];
    const float* Wo = (const float*)d_in[4];
    float* out = (float*)d_out;

    void *pxh, *paoh, *pwh;
    cudaGetSymbolAddress(&pxh,  g_xh);
    cudaGetSymbolAddress(&paoh, g_aoh);
    cudaGetSymbolAddress(&pwh,  g_wh);

    __half* xh  = (__half*)pxh;
    __half* aoh = (__half*)paoh;
    __half* wh  = (__half*)pwh;

    cudaFuncSetAttribute(gemm_f16,
                         cudaFuncAttributeMaxDynamicSharedMemorySize, G_SMEM);
    cudaFuncSetAttribute(gemm_qkv,
                         cudaFuncAttributeMaxDynamicSharedMemorySize, G_SMEM);
    cudaFuncSetAttribute(flash_attn_f16,
                         cudaFuncAttributeMaxDynamicSharedMemorySize, A_SMEM);

    const int total4 = N4X + 4 * N4W;
    convert_all<<<(total4 + 255) / 256, 256>>>(x, Wq, Wk, Wv, Wo);

    dim3 qkvgrid(K3 / BN, M_ROWS / BM);      // (24, 64)
    gemm_qkv<<<qkvgrid, 256, G_SMEM>>>(xh, wh);

    dim3 fgrid(NQT, N_HEADS, B_SZ);          // (16, 16, 4)
    flash_attn_f16<<<fgrid, 256, A_SMEM>>>();

    dim3 ogrid(D_MODEL / BN, M_ROWS / BM);   // (8, 64)
    gemm_f16<<<ogrid, 256, G_SMEM>>>(aoh, wh + 3 * (size_t)D_MODEL * D_MODEL, out, D_MODEL);
}

// round 11
// speedup vs baseline: 1.2620x; 1.0836x over previous
#include <cuda_runtime.h>
#include <cuda_fp16.h>
#include <cstdint>
#include <math.h>

#define D_MODEL 1024
#define N_HEADS 16
#define D_HEAD  64
#define B_SZ    4
#define SEQ     2048
#define M_ROWS  (B_SZ * SEQ)   // 8192
#define K3      (3 * D_MODEL)  // 3072
#define K2      (2 * D_MODEL)  // 2048
#define WROW    D_MODEL
#define NQT     (SEQ / 128)    // 16
#define N4X     (M_ROWS * D_MODEL / 4)
#define N4W     (D_MODEL * D_MODEL / 4)    // 2^18

// ---------------- scratch (__device__ globals) ------------------------------
__device__ __half g_xh [M_ROWS * K2];
__device__ __half g_aoh[M_ROWS * K2];
__device__ __half g_wh [4 * D_MODEL * D_MODEL];
__device__ __half g_Qp [B_SZ * N_HEADS * NQT * 16384];
__device__ __half g_KVp[B_SZ * N_HEADS * NQT * 24576];

// ---------------- helpers ----------------------------------------------------
__device__ __forceinline__ uint32_t smem_u32(const void* p) {
    uint32_t a;
    asm("{ .reg .u64 t; cvta.to.shared.u64 t, %1; cvt.u32.u64 %0, t; }" : "=r"(a) : "l"(p));
    return a;
}
__device__ __forceinline__ void cp_async16(uint32_t s, const void* g) {
    asm volatile("cp.async.cg.shared.global [%0], [%1], 16;" :: "r"(s), "l"(g));
}
#define CP_COMMIT() asm volatile("cp.async.commit_group;" ::: "memory")
#define CP_WAIT0()  asm volatile("cp.async.wait_group 0;" ::: "memory")
#define CP_WAIT1()  asm volatile("cp.async.wait_group 1;" ::: "memory")

__device__ __forceinline__ void ldsm4(uint32_t& r0, uint32_t& r1, uint32_t& r2, uint32_t& r3,
                                      uint32_t addr) {
    asm volatile("ldmatrix.sync.aligned.m8n8.x4.shared.b16 {%0,%1,%2,%3}, [%4];"
                 : "=r"(r0), "=r"(r1), "=r"(r2), "=r"(r3) : "r"(addr));
}
__device__ __forceinline__ void mma16816h(float* c, uint32_t a0, uint32_t a1,
                                          uint32_t a2, uint32_t a3,
                                          uint32_t b0, uint32_t b1) {
    asm volatile("mma.sync.aligned.m16n8k16.row.col.f32.f16.f16.f32 "
                 "{%0,%1,%2,%3}, {%4,%5,%6,%7}, {%8,%9}, {%0,%1,%2,%3};"
                 : "+f"(c[0]), "+f"(c[1]), "+f"(c[2]), "+f"(c[3])
                 : "r"(a0), "r"(a1), "r"(a2), "r"(a3), "r"(b0), "r"(b1));
}
__device__ __forceinline__ uint32_t swz128(int row, int c) {
    return (uint32_t)(row * 128 + ((c ^ (row & 7)) << 4));
}
__device__ __forceinline__ uint32_t swzV(int row, int c) {
    return (uint32_t)(row * 256 + ((c ^ (row & 7)) << 4));
}
__device__ __forceinline__ uint32_t pack_h2(float a, float b) {
    __half2 h = __floats2half2_rn(a, b);
    return *(uint32_t*)&h;
}
__device__ __forceinline__ float ex2(float x) {
    float y;
    asm("ex2.approx.ftz.f32 %0, %1;" : "=f"(y) : "f"(x));
    return y;
}

// ---------------- fused conversions ------------------------------------------
__global__ void convert_all(const float* __restrict__ x,
                            const float* __restrict__ w0, const float* __restrict__ w1,
                            const float* __restrict__ w2, const float* __restrict__ w3)
{
    int i = blockIdx.x * 256 + threadIdx.x;
    if (i < N4X) {
        int r = i >> 8;
        int c = (i & 255) * 4;
        float4 v = ((const float4*)x)[i];
        float f[4] = {v.x, v.y, v.z, v.w};
        ushort hb[4], lb[4];
#pragma unroll
        for (int e = 0; e < 4; e++) {
            __half hh = __float2half_rn(f[e]);
            hb[e] = __half_as_ushort(hh);
            lb[e] = __half_as_ushort(__float2half_rn(f[e] - __half2float(hh)));
        }
        size_t base = (size_t)r * K2 + c;
        *(ushort4*)(g_xh + base)           = *(ushort4*)hb;
        *(ushort4*)(g_xh + base + D_MODEL) = *(ushort4*)lb;
    } else {
        int j = i - N4X;
        int w = j >> 18;
        int idx = j & (N4W - 1);
        const float* src = (w == 0) ? w0 : (w == 1) ? w1 : (w == 2) ? w2 : w3;
        float4 v = ((const float4*)src)[idx];
        ushort hb[4] = {
            __half_as_ushort(__float2half_rn(v.x)),
            __half_as_ushort(__float2half_rn(v.y)),
            __half_as_ushort(__float2half_rn(v.z)),
            __half_as_ushort(__float2half_rn(v.w))};
        *(ushort4*)(g_wh + (size_t)w * D_MODEL * D_MODEL + (size_t)idx * 4) = *(ushort4*)hb;
    }
}

// ---------------- fp16 NT GEMM core: BKT=64, 3 stages, 2 CTAs/SM -------------
#define BM 128
#define BN 128
#define BKT 64
#define STAGES 3
#define STG_HALF 16384
#define STAGE_BYTES 32768
#define G_SMEM (STAGES * STAGE_BYTES)
#define NKT (K2 / BKT)                   // 32

__device__ __forceinline__ void gemm_mainloop(
    const __half* __restrict__ A, const __half* __restrict__ B,
    char* sm, float acc[2][8][4], int m0, int n0)
{
    const uint32_t sbase = smem_u32(sm);
    const int tid  = threadIdx.x;
    const int lane = tid & 31;
    const int wid  = tid >> 5;
    const int wm   = wid & 3;
    const int wn   = wid >> 2;

    const int lr = tid >> 3, lc = tid & 7;
    const __half* Ag = A + (size_t)(m0 + lr) * K2 + lc * 8;
    const __half* Bg = B + (size_t)(n0 + lr) * WROW + lc * 8;

#pragma unroll
    for (int i = 0; i < 2; i++)
#pragma unroll
        for (int j = 0; j < 8; j++)
#pragma unroll
            for (int q = 0; q < 4; q++) acc[i][j][q] = 0.f;

#pragma unroll
    for (int s = 0; s < STAGES - 1; s++) {
        uint32_t st = sbase + s * STAGE_BYTES;
        int ko = s * BKT;
#pragma unroll
        for (int it = 0; it < 4; it++) {
            int r = lr + it * 32;
            uint32_t so = swz128(r, lc);
            cp_async16(st + so,            Ag + (size_t)(it * 32) * K2 + ko);
            cp_async16(st + STG_HALF + so, Bg + (size_t)(it * 32) * WROW + (ko & 1023));
        }
        CP_COMMIT();
    }

    const int aRow = wm * 32 + (lane & 15);
    const int aCsel = lane >> 4;
    const int bRow = wn * 64 + (lane & 7) + ((lane >> 4) << 3);
    const int bCsel = (lane >> 3) & 1;

    for (int kt = 0; kt < NKT; kt++) {
        CP_WAIT1();
        __syncthreads();

        if (kt + STAGES - 1 < NKT) {
            int s = (kt + STAGES - 1) % STAGES;
            int ko = (kt + STAGES - 1) * BKT;
            uint32_t st = sbase + s * STAGE_BYTES;
#pragma unroll
            for (int it = 0; it < 4; it++) {
                int r = lr + it * 32;
                uint32_t so = swz128(r, lc);
                cp_async16(st + so,            Ag + (size_t)(it * 32) * K2 + ko);
                cp_async16(st + STG_HALF + so, Bg + (size_t)(it * 32) * WROW + (ko & 1023));
            }
        }
        CP_COMMIT();

        const uint32_t stA = sbase + (kt % STAGES) * STAGE_BYTES;
        const uint32_t stB = stA + STG_HALF;

#pragma unroll
        for (int k16 = 0; k16 < 4; k16++) {
            const int kc = k16 * 2;
            uint32_t af[2][4];
#pragma unroll
            for (int i = 0; i < 2; i++) {
                int r = aRow + i * 16;
                ldsm4(af[i][0], af[i][1], af[i][2], af[i][3],
                      stA + swz128(r, kc + aCsel));
            }
            uint32_t bf[4][4];
#pragma unroll
            for (int j = 0; j < 4; j++) {
                int r = bRow + j * 16;
                ldsm4(bf[j][0], bf[j][1], bf[j][2], bf[j][3],
                      stB + swz128(r, kc + bCsel));
            }
#pragma unroll
            for (int i = 0; i < 2; i++)
#pragma unroll
                for (int j = 0; j < 4; j++) {
                    mma16816h(acc[i][2*j+0], af[i][0], af[i][1], af[i][2], af[i][3],
                              bf[j][0], bf[j][1]);
                    mma16816h(acc[i][2*j+1], af[i][0], af[i][1], af[i][2], af[i][3],
                              bf[j][2], bf[j][3]);
                }
        }
    }
}

__global__ __launch_bounds__(256, 2)
void gemm_f16(const __half* __restrict__ A, const __half* __restrict__ B,
              float* __restrict__ C, int cpitch)
{
    extern __shared__ __align__(128) char sm[];
    const int m0 = blockIdx.y * BM;
    const int n0 = blockIdx.x * BN;
    float acc[2][8][4];
    gemm_mainloop(A, B, sm, acc, m0, n0);

    const int lane = threadIdx.x & 31;
    const int wid  = threadIdx.x >> 5;
    const int wm = wid & 3, wn = wid >> 2;
    const int gid = lane >> 2, q = lane & 3;
#pragma unroll
    for (int i = 0; i < 2; i++) {
        int r0 = m0 + wm * 32 + i * 16 + gid;
#pragma unroll
        for (int j = 0; j < 8; j++) {
            int col = n0 + wn * 64 + j * 8 + q * 2;
            *(float2*)(C + (size_t)r0 * cpitch + col) =
                make_float2(acc[i][j][0], acc[i][j][1]);
            *(float2*)(C + (size_t)(r0 + 8) * cpitch + col) =
                make_float2(acc[i][j][2], acc[i][j][3]);
        }
    }
}

__global__ __launch_bounds__(256, 2)
void gemm_qkv(const __half* __restrict__ A, const __half* __restrict__ B)
{
    extern __shared__ __align__(128) char sm[];
    const int m0 = blockIdx.y * BM;
    const int n0 = blockIdx.x * BN;
    float acc[2][8][4];
    gemm_mainloop(A, B, sm, acc, m0, n0);

    const int lane = threadIdx.x & 31;
    const int wid  = threadIdx.x >> 5;
    const int wm = wid & 3, wn = wid >> 2;
    const int gid = lane >> 2, q = lane & 3;

    const int bb = m0 >> 11;
    const int t  = (m0 & 2047) >> 7;
    const int region = n0 >> 10;
    const int nloc = n0 & 1023;
    const float QSCALE = 0.125f * 1.4426950408889634f;

#pragma unroll
    for (int i = 0; i < 2; i++) {
        const int lrow0 = wm * 32 + i * 16 + gid;
        const int lrow1 = lrow0 + 8;
#pragma unroll
        for (int j = 0; j < 8; j++) {
            const int c128 = wn * 64 + j * 8 + q * 2;
            const int n = nloc + c128;
            const int h = n >> 6;
            const int d = n & 63;
            const size_t bh = (size_t)(bb * N_HEADS + h) * NQT + t;

            if (region == 0) {
                char* qd = (char*)(g_Qp + bh * 16384);
                uint32_t o0 = swz128(lrow0, d >> 3) + (d & 7) * 2;
                uint32_t o1 = swz128(lrow1, d >> 3) + (d & 7) * 2;
                float a0 = acc[i][j][0] * QSCALE, a1 = acc[i][j][1] * QSCALE;
                float b0 = acc[i][j][2] * QSCALE, b1 = acc[i][j][3] * QSCALE;
                uint32_t h0 = pack_h2(a0, a1), h1 = pack_h2(b0, b1);
                __half2 hh0 = *(__half2*)&h0, hh1 = *(__half2*)&h1;
                uint32_t l0 = pack_h2(a0 - __low2float(hh0), a1 - __high2float(hh0));
                uint32_t l1 = pack_h2(b0 - __low2float(hh1), b1 - __high2float(hh1));
                *(uint32_t*)(qd + o0)         = h0;
                *(uint32_t*)(qd + 16384 + o0) = l0;
                *(uint32_t*)(qd + o1)         = h1;
                *(uint32_t*)(qd + 16384 + o1) = l1;
            } else if (region == 1) {
                char* kd = (char*)(g_KVp + bh * 24576);
                uint32_t o0 = swz128(lrow0, d >> 3) + (d & 7) * 2;
                uint32_t o1 = swz128(lrow1, d >> 3) + (d & 7) * 2;
                float a0 = acc[i][j][0], a1 = acc[i][j][1];
                float b0 = acc[i][j][2], b1 = acc[i][j][3];
                uint32_t h0 = pack_h2(a0, a1), h1 = pack_h2(b0, b1);
                __half2 hh0 = *(__half2*)&h0, hh1 = *(__half2*)&h1;
                uint32_t l0 = pack_h2(a0 - __low2float(hh0), a1 - __high2float(hh0));
                uint32_t l1 = pack_h2(b0 - __low2float(hh1), b1 - __high2float(hh1));
                *(uint32_t*)(kd + o0)         = h0;
                *(uint32_t*)(kd + 16384 + o0) = l0;
                *(uint32_t*)(kd + o1)         = h1;
                *(uint32_t*)(kd + 16384 + o1) = l1;
            } else {
                char* vd = (char*)(g_KVp + bh * 24576) + 32768;
                uint32_t oa0 = swzV(d,     lrow0 >> 3) + (lrow0 & 7) * 2;
                uint32_t oa1 = swzV(d + 1, lrow0 >> 3) + (lrow0 & 7) * 2;
                uint32_t ob0 = swzV(d,     lrow1 >> 3) + (lrow1 & 7) * 2;
                uint32_t ob1 = swzV(d + 1, lrow1 >> 3) + (lrow1 & 7) * 2;
                *(ushort*)(vd + oa0) = __half_as_ushort(__float2half_rn(acc[i][j][0]));
                *(ushort*)(vd + oa1) = __half_as_ushort(__float2half_rn(acc[i][j][1]));
                *(ushort*)(vd + ob0) = __half_as_ushort(__float2half_rn(acc[i][j][2]));
                *(ushort*)(vd + ob1) = __half_as_ushort(__float2half_rn(acc[i][j][3]));
            }
        }
    }
}

// ---------------------------------------------------------------------------
// Flash attention: 3-deep KV prefetch; PV single-term (P fp16, no lo).
// ---------------------------------------------------------------------------
#define SM_Q   0
#define SM_ST  32768
#define STG    49152
#define A_SMEM (32768 + 3 * 49152)    // 180224

__global__ __launch_bounds__(256, 1)
void flash_attn_f16()
{
    extern __shared__ __align__(128) char smc[];
    const uint32_t sb = smem_u32(smc);
    const int tid  = threadIdx.x;
    const int lane = tid & 31;
    const int wid  = tid >> 5;
    const int gid  = lane >> 2;
    const int qq   = lane & 3;
    const int qt = gridDim.x - 1 - blockIdx.x;
    const int h  = blockIdx.y;
    const int b  = blockIdx.z;
    const int q0 = qt * 128;
    const size_t bhbase = (size_t)(b * N_HEADS + h) * NQT;

    // prologue: group0 = Q + KV0; group1 = KV1 (if any)
    {
        const char* qs = (const char*)(g_Qp + (bhbase + qt) * 16384);
#pragma unroll
        for (int i = 0; i < 8; i++) {
            uint32_t off = (tid + i * 256) * 16;
            cp_async16(sb + SM_Q + off, qs + off);
        }
        const char* kvs = (const char*)(g_KVp + bhbase * 24576);
#pragma unroll
        for (int i = 0; i < 12; i++) {
            uint32_t off = (tid + i * 256) * 16;
            cp_async16(sb + SM_ST + off, kvs + off);
        }
        CP_COMMIT();
        if (qt >= 1) {
            const char* kv1 = (const char*)(g_KVp + (bhbase + 1) * 24576);
#pragma unroll
            for (int i = 0; i < 12; i++) {
                uint32_t off = (tid + i * 256) * 16;
                cp_async16(sb + SM_ST + STG + off, kv1 + off);
            }
            CP_COMMIT();
        }
    }
    if (qt >= 1) { CP_WAIT1(); } else { CP_WAIT0(); }
    __syncthreads();

    const int aRow = wid * 16 + (lane & 15);
    const int aCsel = lane >> 4;
    uint32_t qh[4][4], ql[4][4];
#pragma unroll
    for (int kt2 = 0; kt2 < 4; kt2++) {
        ldsm4(qh[kt2][0], qh[kt2][1], qh[kt2][2], qh[kt2][3],
              sb + SM_Q + swz128(aRow, kt2 * 2 + aCsel));
        ldsm4(ql[kt2][0], ql[kt2][1], ql[kt2][2], ql[kt2][3],
              sb + SM_Q + 16384 + swz128(aRow, kt2 * 2 + aCsel));
    }

    float m0r = -1e30f, m1r = -1e30f, l0r = 0.f, l1r = 0.f;
    float oacc[8][4];
#pragma unroll
    for (int j = 0; j < 8; j++)
#pragma unroll
        for (int q2 = 0; q2 < 4; q2++) oacc[j][q2] = 0.f;

    const int bRowBase = (lane & 7) + ((lane >> 4) << 3);
    const int bCsel = (lane >> 3) & 1;
    const int row0 = wid * 16 + gid;
    const int row1 = row0 + 8;

    for (int t = 0; t <= qt; t++) {
        if (t > 0) {
            if (t < qt) { CP_WAIT1(); } else { CP_WAIT0(); }
            __syncthreads();
        }
        if (t + 2 <= qt) {
            const char* kvs = (const char*)(g_KVp + (bhbase + t + 2) * 24576);
            uint32_t dst = sb + SM_ST + ((t + 2) % 3) * STG;
#pragma unroll
            for (int i = 0; i < 12; i++) {
                uint32_t off = (tid + i * 256) * 16;
                cp_async16(dst + off, kvs + off);
            }
            CP_COMMIT();
        }

        const uint32_t kb = sb + SM_ST + (t % 3) * STG;
        const uint32_t lb = kb + 16384;
        const uint32_t vbse = kb + 32768;

        float sacc[16][4];
#pragma unroll
        for (int j = 0; j < 16; j++)
#pragma unroll
            for (int q2 = 0; q2 < 4; q2++) sacc[j][q2] = 0.f;

#pragma unroll
        for (int kt2 = 0; kt2 < 4; kt2++) {
#pragma unroll
            for (int jt2 = 0; jt2 < 8; jt2++) {
                int r = jt2 * 16 + bRowBase;
                uint32_t kc = kt2 * 2 + bCsel;
                uint32_t bh4[4], bl4[4];
                ldsm4(bh4[0], bh4[1], bh4[2], bh4[3], kb + swz128(r, kc));
                ldsm4(bl4[0], bl4[1], bl4[2], bl4[3], lb + swz128(r, kc));
                mma16816h(sacc[2*jt2],   qh[kt2][0], qh[kt2][1], qh[kt2][2], qh[kt2][3], bh4[0], bh4[1]);
                mma16816h(sacc[2*jt2+1], qh[kt2][0], qh[kt2][1], qh[kt2][2], qh[kt2][3], bh4[2], bh4[3]);
                mma16816h(sacc[2*jt2],   ql[kt2][0], ql[kt2][1], ql[kt2][2], ql[kt2][3], bh4[0], bh4[1]);
                mma16816h(sacc[2*jt2+1], ql[kt2][0], ql[kt2][1], ql[kt2][2], ql[kt2][3], bh4[2], bh4[3]);
                mma16816h(sacc[2*jt2],   qh[kt2][0], qh[kt2][1], qh[kt2][2], qh[kt2][3], bl4[0], bl4[1]);
                mma16816h(sacc[2*jt2+1], qh[kt2][0], qh[kt2][1], qh[kt2][2], qh[kt2][3], bl4[2], bl4[3]);
            }
        }

        if (t == qt) {
#pragma unroll
            for (int j = 0; j < 16; j++) {
                int c0 = j * 8 + qq * 2;
                if (c0 > row0)     sacc[j][0] = -1e30f;
                if (c0 + 1 > row0) sacc[j][1] = -1e30f;
                if (c0 > row1)     sacc[j][2] = -1e30f;
                if (c0 + 1 > row1) sacc[j][3] = -1e30f;
            }
        }

        float mx0 = -1e30f, mx1 = -1e30f;
#pragma unroll
        for (int j = 0; j < 16; j++) {
            mx0 = fmaxf(mx0, fmaxf(sacc[j][0], sacc[j][1]));
            mx1 = fmaxf(mx1, fmaxf(sacc[j][2], sacc[j][3]));
        }
        mx0 = fmaxf(mx0, __shfl_xor_sync(0xffffffffu, mx0, 1));
        mx0 = fmaxf(mx0, __shfl_xor_sync(0xffffffffu, mx0, 2));
        mx1 = fmaxf(mx1, __shfl_xor_sync(0xffffffffu, mx1, 1));
        mx1 = fmaxf(mx1, __shfl_xor_sync(0xffffffffu, mx1, 2));

        float mn0 = fmaxf(m0r, mx0), mn1 = fmaxf(m1r, mx1);
        float cr0 = ex2(m0r - mn0), cr1 = ex2(m1r - mn1);
        float sum0 = 0.f, sum1 = 0.f;
#pragma unroll
        for (int j = 0; j < 16; j++) {
            sacc[j][0] = ex2(sacc[j][0] - mn0);
            sacc[j][1] = ex2(sacc[j][1] - mn0);
            sacc[j][2] = ex2(sacc[j][2] - mn1);
            sacc[j][3] = ex2(sacc[j][3] - mn1);
            sum0 += sacc[j][0] + sacc[j][1];
            sum1 += sacc[j][2] + sacc[j][3];
        }
        sum0 += __shfl_xor_sync(0xffffffffu, sum0, 1);
        sum0 += __shfl_xor_sync(0xffffffffu, sum0, 2);
        sum1 += __shfl_xor_sync(0xffffffffu, sum1, 1);
        sum1 += __shfl_xor_sync(0xffffffffu, sum1, 2);

        l0r = l0r * cr0 + sum0;  m0r = mn0;
        l1r = l1r * cr1 + sum1;  m1r = mn1;
#pragma unroll
        for (int j = 0; j < 8; j++) {
            oacc[j][0] *= cr0; oacc[j][1] *= cr0;
            oacc[j][2] *= cr1; oacc[j][3] *= cr1;
        }

        // ---- O += P V (single fp16 P term) ----
#pragma unroll
        for (int kt2 = 0; kt2 < 8; kt2++) {
            const int jA = 2 * kt2, jB = 2 * kt2 + 1;
            uint32_t ph[4];
            ph[0] = pack_h2(sacc[jA][0], sacc[jA][1]);
            ph[1] = pack_h2(sacc[jA][2], sacc[jA][3]);
            ph[2] = pack_h2(sacc[jB][0], sacc[jB][1]);
            ph[3] = pack_h2(sacc[jB][2], sacc[jB][3]);
#pragma unroll
            for (int nt2 = 0; nt2 < 4; nt2++) {
                int r = nt2 * 16 + bRowBase;
                uint32_t vc = kt2 * 2 + bCsel;
                uint32_t bv[4];
                ldsm4(bv[0], bv[1], bv[2], bv[3], vbse + swzV(r, vc));
                mma16816h(oacc[2*nt2],   ph[0], ph[1], ph[2], ph[3], bv[0], bv[1]);
                mma16816h(oacc[2*nt2+1], ph[0], ph[1], ph[2], ph[3], bv[2], bv[3]);
            }
        }
    }

    const float inv0 = 1.0f / l0r, inv1 = 1.0f / l1r;
    const size_t gr0 = (size_t)(b * SEQ + q0 + row0);
    const size_t gr1 = (size_t)(b * SEQ + q0 + row1);
#pragma unroll
    for (int nt = 0; nt < 8; nt++) {
        int col = h * D_HEAD + nt * 8 + qq * 2;
        float a0 = oacc[nt][0] * inv0, a1 = oacc[nt][1] * inv0;
        float b0f = oacc[nt][2] * inv1, b1f = oacc[nt][3] * inv1;
        uint32_t h0 = pack_h2(a0, a1), h1 = pack_h2(b0f, b1f);
        __half2 hh0 = *(__half2*)&h0, hh1 = *(__half2*)&h1;
        uint32_t l0 = pack_h2(a0 - __low2float(hh0), a1 - __high2float(hh0));
        uint32_t l1 = pack_h2(b0f - __low2float(hh1), b1f - __high2float(hh1));
        *(uint32_t*)(g_aoh + gr0 * K2 + col)           = h0;
        *(uint32_t*)(g_aoh + gr0 * K2 + D_MODEL + col) = l0;
        *(uint32_t*)(g_aoh + gr1 * K2 + col)           = h1;
        *(uint32_t*)(g_aoh + gr1 * K2 + D_MODEL + col) = l1;
    }
}

// ---------------------------------------------------------------------------
extern "C" void kernel_launch(void* const* d_in, const int* in_sizes, int n_in,
                              void* d_out, int out_size)
{
    const float* x  = (const float*)d_in[0];
    const float* Wq = (const float*)d_in[1];
    const float* Wk = (const float*)d_in[2];
    const float* Wv = (const float*)d_in[3];
    const float* Wo = (const float*)d_in[4];
    float* out = (float*)d_out;

    void *pxh, *paoh, *pwh;
    cudaGetSymbolAddress(&pxh,  g_xh);
    cudaGetSymbolAddress(&paoh, g_aoh);
    cudaGetSymbolAddress(&pwh,  g_wh);

    __half* xh  = (__half*)pxh;
    __half* aoh = (__half*)paoh;
    __half* wh  = (__half*)pwh;

    cudaFuncSetAttribute(gemm_f16,
                         cudaFuncAttributeMaxDynamicSharedMemorySize, G_SMEM);
    cudaFuncSetAttribute(gemm_qkv,
                         cudaFuncAttributeMaxDynamicSharedMemorySize, G_SMEM);
    cudaFuncSetAttribute(flash_attn_f16,
                         cudaFuncAttributeMaxDynamicSharedMemorySize, A_SMEM);

    const int total4 = N4X + 4 * N4W;
    convert_all<<<(total4 + 255) / 256, 256>>>(x, Wq, Wk, Wv, Wo);

    dim3 qkvgrid(K3 / BN, M_ROWS / BM);      // (24, 64)
    gemm_qkv<<<qkvgrid, 256, G_SMEM>>>(xh, wh);

    dim3 fgrid(NQT, N_HEADS, B_SZ);          // (16, 16, 4)
    flash_attn_f16<<<fgrid, 256, A_SMEM>>>();

    dim3 ogrid(D_MODEL / BN, M_ROWS / BM);   // (8, 64)
    gemm_f16<<<ogrid, 256, G_SMEM>>>(aoh, wh + 3 * (size_t)D_MODEL * D_MODEL, out, D_MODEL);
}

// round 12
// speedup vs baseline: 1.3741x; 1.0888x over previous
#include <cuda_runtime.h>
#include <cuda_fp16.h>
#include <cstdint>
#include <math.h>

#define D_MODEL 1024
#define N_HEADS 16
#define D_HEAD  64
#define B_SZ    4
#define SEQ     2048
#define M_ROWS  (B_SZ * SEQ)   // 8192
#define K3      (3 * D_MODEL)  // 3072
#define K2      (2 * D_MODEL)  // 2048
#define WROW    D_MODEL
#define NQT     (SEQ / 128)    // 16
#define N4X     (M_ROWS * D_MODEL / 4)
#define N4W     (D_MODEL * D_MODEL / 4)    // 2^18

// ---------------- scratch (__device__ globals) ------------------------------
__device__ __half g_xh [M_ROWS * K2];                 // x split [hi | lo]
__device__ __half g_aoh[M_ROWS * D_MODEL];            // attn out, single fp16
__device__ __half g_wh [4 * D_MODEL * D_MODEL];
__device__ __half g_Qp [B_SZ * N_HEADS * NQT * 16384];
__device__ __half g_KVp[B_SZ * N_HEADS * NQT * 24576];

// ---------------- helpers ----------------------------------------------------
__device__ __forceinline__ uint32_t smem_u32(const void* p) {
    uint32_t a;
    asm("{ .reg .u64 t; cvta.to.shared.u64 t, %1; cvt.u32.u64 %0, t; }" : "=r"(a) : "l"(p));
    return a;
}
__device__ __forceinline__ void cp_async16(uint32_t s, const void* g) {
    asm volatile("cp.async.cg.shared.global [%0], [%1], 16;" :: "r"(s), "l"(g));
}
#define CP_COMMIT() asm volatile("cp.async.commit_group;" ::: "memory")
#define CP_WAIT0()  asm volatile("cp.async.wait_group 0;" ::: "memory")
#define CP_WAIT1()  asm volatile("cp.async.wait_group 1;" ::: "memory")

__device__ __forceinline__ void ldsm4(uint32_t& r0, uint32_t& r1, uint32_t& r2, uint32_t& r3,
                                      uint32_t addr) {
    asm volatile("ldmatrix.sync.aligned.m8n8.x4.shared.b16 {%0,%1,%2,%3}, [%4];"
                 : "=r"(r0), "=r"(r1), "=r"(r2), "=r"(r3) : "r"(addr));
}
__device__ __forceinline__ void mma16816h(float* c, uint32_t a0, uint32_t a1,
                                          uint32_t a2, uint32_t a3,
                                          uint32_t b0, uint32_t b1) {
    asm volatile("mma.sync.aligned.m16n8k16.row.col.f32.f16.f16.f32 "
                 "{%0,%1,%2,%3}, {%4,%5,%6,%7}, {%8,%9}, {%0,%1,%2,%3};"
                 : "+f"(c[0]), "+f"(c[1]), "+f"(c[2]), "+f"(c[3])
                 : "r"(a0), "r"(a1), "r"(a2), "r"(a3), "r"(b0), "r"(b1));
}
__device__ __forceinline__ uint32_t swz128(int row, int c) {
    return (uint32_t)(row * 128 + ((c ^ (row & 7)) << 4));
}
__device__ __forceinline__ uint32_t swzV(int row, int c) {
    return (uint32_t)(row * 256 + ((c ^ (row & 7)) << 4));
}
__device__ __forceinline__ uint32_t pack_h2(float a, float b) {
    __half2 h = __floats2half2_rn(a, b);
    return *(uint32_t*)&h;
}
__device__ __forceinline__ float ex2(float x) {
    float y;
    asm("ex2.approx.ftz.f32 %0, %1;" : "=f"(y) : "f"(x));
    return y;
}

// ---------------- fused conversions ------------------------------------------
__global__ void convert_all(const float* __restrict__ x,
                            const float* __restrict__ w0, const float* __restrict__ w1,
                            const float* __restrict__ w2, const float* __restrict__ w3)
{
    int i = blockIdx.x * 256 + threadIdx.x;
    if (i < N4X) {
        int r = i >> 8;
        int c = (i & 255) * 4;
        float4 v = ((const float4*)x)[i];
        float f[4] = {v.x, v.y, v.z, v.w};
        ushort hb[4], lb[4];
#pragma unroll
        for (int e = 0; e < 4; e++) {
            __half hh = __float2half_rn(f[e]);
            hb[e] = __half_as_ushort(hh);
            lb[e] = __half_as_ushort(__float2half_rn(f[e] - __half2float(hh)));
        }
        size_t base = (size_t)r * K2 + c;
        *(ushort4*)(g_xh + base)           = *(ushort4*)hb;
        *(ushort4*)(g_xh + base + D_MODEL) = *(ushort4*)lb;
    } else {
        int j = i - N4X;
        int w = j >> 18;
        int idx = j & (N4W - 1);
        const float* src = (w == 0) ? w0 : (w == 1) ? w1 : (w == 2) ? w2 : w3;
        float4 v = ((const float4*)src)[idx];
        ushort hb[4] = {
            __half_as_ushort(__float2half_rn(v.x)),
            __half_as_ushort(__float2half_rn(v.y)),
            __half_as_ushort(__float2half_rn(v.z)),
            __half_as_ushort(__float2half_rn(v.w))};
        *(ushort4*)(g_wh + (size_t)w * D_MODEL * D_MODEL + (size_t)idx * 4) = *(ushort4*)hb;
    }
}

// ---------------- fp16 NT GEMM core (templated K) ----------------------------
#define BM 128
#define BN 128
#define BKT 64
#define STAGES 3
#define STG_HALF 16384
#define STAGE_BYTES 32768
#define G_SMEM (STAGES * STAGE_BYTES)

template <int NKT_, int APITCH>
__device__ __forceinline__ void gemm_mainloop(
    const __half* __restrict__ A, const __half* __restrict__ B,
    char* sm, float acc[2][8][4], int m0, int n0)
{
    const uint32_t sbase = smem_u32(sm);
    const int tid  = threadIdx.x;
    const int lane = tid & 31;
    const int wid  = tid >> 5;
    const int wm   = wid & 3;
    const int wn   = wid >> 2;

    const int lr = tid >> 3, lc = tid & 7;
    const __half* Ag = A + (size_t)(m0 + lr) * APITCH + lc * 8;
    const __half* Bg = B + (size_t)(n0 + lr) * WROW + lc * 8;

#pragma unroll
    for (int i = 0; i < 2; i++)
#pragma unroll
        for (int j = 0; j < 8; j++)
#pragma unroll
            for (int q = 0; q < 4; q++) acc[i][j][q] = 0.f;

#pragma unroll
    for (int s = 0; s < STAGES - 1; s++) {
        uint32_t st = sbase + s * STAGE_BYTES;
        int ko = s * BKT;
#pragma unroll
        for (int it = 0; it < 4; it++) {
            int r = lr + it * 32;
            uint32_t so = swz128(r, lc);
            cp_async16(st + so,            Ag + (size_t)(it * 32) * APITCH + ko);
            cp_async16(st + STG_HALF + so, Bg + (size_t)(it * 32) * WROW + (ko & 1023));
        }
        CP_COMMIT();
    }

    const int aRow = wm * 32 + (lane & 15);
    const int aCsel = lane >> 4;
    const int bRow = wn * 64 + (lane & 7) + ((lane >> 4) << 3);
    const int bCsel = (lane >> 3) & 1;

    for (int kt = 0; kt < NKT_; kt++) {
        CP_WAIT1();
        __syncthreads();

        if (kt + STAGES - 1 < NKT_) {
            int s = (kt + STAGES - 1) % STAGES;
            int ko = (kt + STAGES - 1) * BKT;
            uint32_t st = sbase + s * STAGE_BYTES;
#pragma unroll
            for (int it = 0; it < 4; it++) {
                int r = lr + it * 32;
                uint32_t so = swz128(r, lc);
                cp_async16(st + so,            Ag + (size_t)(it * 32) * APITCH + ko);
                cp_async16(st + STG_HALF + so, Bg + (size_t)(it * 32) * WROW + (ko & 1023));
            }
        }
        CP_COMMIT();

        const uint32_t stA = sbase + (kt % STAGES) * STAGE_BYTES;
        const uint32_t stB = stA + STG_HALF;

#pragma unroll
        for (int k16 = 0; k16 < 4; k16++) {
            const int kc = k16 * 2;
            uint32_t af[2][4];
#pragma unroll
            for (int i = 0; i < 2; i++) {
                int r = aRow + i * 16;
                ldsm4(af[i][0], af[i][1], af[i][2], af[i][3],
                      stA + swz128(r, kc + aCsel));
            }
            uint32_t bf[4][4];
#pragma unroll
            for (int j = 0; j < 4; j++) {
                int r = bRow + j * 16;
                ldsm4(bf[j][0], bf[j][1], bf[j][2], bf[j][3],
                      stB + swz128(r, kc + bCsel));
            }
#pragma unroll
            for (int i = 0; i < 2; i++)
#pragma unroll
                for (int j = 0; j < 4; j++) {
                    mma16816h(acc[i][2*j+0], af[i][0], af[i][1], af[i][2], af[i][3],
                              bf[j][0], bf[j][1]);
                    mma16816h(acc[i][2*j+1], af[i][0], af[i][1], af[i][2], af[i][3],
                              bf[j][2], bf[j][3]);
                }
        }
    }
}

// O projection: K=1024 (single fp16 A), fp32 output.
__global__ __launch_bounds__(256, 2)
void gemm_o(const __half* __restrict__ A, const __half* __restrict__ B,
            float* __restrict__ C)
{
    extern __shared__ __align__(128) char sm[];
    const int m0 = blockIdx.y * BM;
    const int n0 = blockIdx.x * BN;
    float acc[2][8][4];
    gemm_mainloop<D_MODEL / BKT, D_MODEL>(A, B, sm, acc, m0, n0);

    const int lane = threadIdx.x & 31;
    const int wid  = threadIdx.x >> 5;
    const int wm = wid & 3, wn = wid >> 2;
    const int gid = lane >> 2, q = lane & 3;
#pragma unroll
    for (int i = 0; i < 2; i++) {
        int r0 = m0 + wm * 32 + i * 16 + gid;
#pragma unroll
        for (int j = 0; j < 8; j++) {
            int col = n0 + wn * 64 + j * 8 + q * 2;
            *(float2*)(C + (size_t)r0 * D_MODEL + col) =
                make_float2(acc[i][j][0], acc[i][j][1]);
            *(float2*)(C + (size_t)(r0 + 8) * D_MODEL + col) =
                make_float2(acc[i][j][2], acc[i][j][3]);
        }
    }
}

// QKV GEMM: K=2048 (hi|lo A), fused prep epilogue.
__global__ __launch_bounds__(256, 2)
void gemm_qkv(const __half* __restrict__ A, const __half* __restrict__ B)
{
    extern __shared__ __align__(128) char sm[];
    const int m0 = blockIdx.y * BM;
    const int n0 = blockIdx.x * BN;
    float acc[2][8][4];
    gemm_mainloop<K2 / BKT, K2>(A, B, sm, acc, m0, n0);

    const int lane = threadIdx.x & 31;
    const int wid  = threadIdx.x >> 5;
    const int wm = wid & 3, wn = wid >> 2;
    const int gid = lane >> 2, q = lane & 3;

    const int bb = m0 >> 11;
    const int t  = (m0 & 2047) >> 7;
    const int region = n0 >> 10;
    const int nloc = n0 & 1023;
    const float QSCALE = 0.125f * 1.4426950408889634f;

#pragma unroll
    for (int i = 0; i < 2; i++) {
        const int lrow0 = wm * 32 + i * 16 + gid;
        const int lrow1 = lrow0 + 8;
#pragma unroll
        for (int j = 0; j < 8; j++) {
            const int c128 = wn * 64 + j * 8 + q * 2;
            const int n = nloc + c128;
            const int h = n >> 6;
            const int d = n & 63;
            const size_t bh = (size_t)(bb * N_HEADS + h) * NQT + t;

            if (region == 0) {
                char* qd = (char*)(g_Qp + bh * 16384);
                uint32_t o0 = swz128(lrow0, d >> 3) + (d & 7) * 2;
                uint32_t o1 = swz128(lrow1, d >> 3) + (d & 7) * 2;
                float a0 = acc[i][j][0] * QSCALE, a1 = acc[i][j][1] * QSCALE;
                float b0 = acc[i][j][2] * QSCALE, b1 = acc[i][j][3] * QSCALE;
                uint32_t h0 = pack_h2(a0, a1), h1 = pack_h2(b0, b1);
                __half2 hh0 = *(__half2*)&h0, hh1 = *(__half2*)&h1;
                uint32_t l0 = pack_h2(a0 - __low2float(hh0), a1 - __high2float(hh0));
                uint32_t l1 = pack_h2(b0 - __low2float(hh1), b1 - __high2float(hh1));
                *(uint32_t*)(qd + o0)         = h0;
                *(uint32_t*)(qd + 16384 + o0) = l0;
                *(uint32_t*)(qd + o1)         = h1;
                *(uint32_t*)(qd + 16384 + o1) = l1;
            } else if (region == 1) {
                char* kd = (char*)(g_KVp + bh * 24576);
                uint32_t o0 = swz128(lrow0, d >> 3) + (d & 7) * 2;
                uint32_t o1 = swz128(lrow1, d >> 3) + (d & 7) * 2;
                float a0 = acc[i][j][0], a1 = acc[i][j][1];
                float b0 = acc[i][j][2], b1 = acc[i][j][3];
                uint32_t h0 = pack_h2(a0, a1), h1 = pack_h2(b0, b1);
                __half2 hh0 = *(__half2*)&h0, hh1 = *(__half2*)&h1;
                uint32_t l0 = pack_h2(a0 - __low2float(hh0), a1 - __high2float(hh0));
                uint32_t l1 = pack_h2(b0 - __low2float(hh1), b1 - __high2float(hh1));
                *(uint32_t*)(kd + o0)         = h0;
                *(uint32_t*)(kd + 16384 + o0) = l0;
                *(uint32_t*)(kd + o1)         = h1;
                *(uint32_t*)(kd + 16384 + o1) = l1;
            } else {
                char* vd = (char*)(g_KVp + bh * 24576) + 32768;
                uint32_t oa0 = swzV(d,     lrow0 >> 3) + (lrow0 & 7) * 2;
                uint32_t oa1 = swzV(d + 1, lrow0 >> 3) + (lrow0 & 7) * 2;
                uint32_t ob0 = swzV(d,     lrow1 >> 3) + (lrow1 & 7) * 2;
                uint32_t ob1 = swzV(d + 1, lrow1 >> 3) + (lrow1 & 7) * 2;
                *(ushort*)(vd + oa0) = __half_as_ushort(__float2half_rn(acc[i][j][0]));
                *(ushort*)(vd + oa1) = __half_as_ushort(__float2half_rn(acc[i][j][1]));
                *(ushort*)(vd + ob0) = __half_as_ushort(__float2half_rn(acc[i][j][2]));
                *(ushort*)(vd + ob1) = __half_as_ushort(__float2half_rn(acc[i][j][3]));
            }
        }
    }
}

// ---------------------------------------------------------------------------
// Flash attention: 3-deep KV prefetch; single-term PV; fp16 output (no split).
// ---------------------------------------------------------------------------
#define SM_Q   0
#define SM_ST  32768
#define STG    49152
#define A_SMEM (32768 + 3 * 49152)

__global__ __launch_bounds__(256, 1)
void flash_attn_f16()
{
    extern __shared__ __align__(128) char smc[];
    const uint32_t sb = smem_u32(smc);
    const int tid  = threadIdx.x;
    const int lane = tid & 31;
    const int wid  = tid >> 5;
    const int gid  = lane >> 2;
    const int qq   = lane & 3;
    const int qt = gridDim.x - 1 - blockIdx.x;
    const int h  = blockIdx.y;
    const int b  = blockIdx.z;
    const int q0 = qt * 128;
    const size_t bhbase = (size_t)(b * N_HEADS + h) * NQT;

    {
        const char* qs = (const char*)(g_Qp + (bhbase + qt) * 16384);
#pragma unroll
        for (int i = 0; i < 8; i++) {
            uint32_t off = (tid + i * 256) * 16;
            cp_async16(sb + SM_Q + off, qs + off);
        }
        const char* kvs = (const char*)(g_KVp + bhbase * 24576);
#pragma unroll
        for (int i = 0; i < 12; i++) {
            uint32_t off = (tid + i * 256) * 16;
            cp_async16(sb + SM_ST + off, kvs + off);
        }
        CP_COMMIT();
        if (qt >= 1) {
            const char* kv1 = (const char*)(g_KVp + (bhbase + 1) * 24576);
#pragma unroll
            for (int i = 0; i < 12; i++) {
                uint32_t off = (tid + i * 256) * 16;
                cp_async16(sb + SM_ST + STG + off, kv1 + off);
            }
            CP_COMMIT();
        }
    }
    if (qt >= 1) { CP_WAIT1(); } else { CP_WAIT0(); }
    __syncthreads();

    const int aRow = wid * 16 + (lane & 15);
    const int aCsel = lane >> 4;
    uint32_t qh[4][4], ql[4][4];
#pragma unroll
    for (int kt2 = 0; kt2 < 4; kt2++) {
        ldsm4(qh[kt2][0], qh[kt2][1], qh[kt2][2], qh[kt2][3],
              sb + SM_Q + swz128(aRow, kt2 * 2 + aCsel));
        ldsm4(ql[kt2][0], ql[kt2][1], ql[kt2][2], ql[kt2][3],
              sb + SM_Q + 16384 + swz128(aRow, kt2 * 2 + aCsel));
    }

    float m0r = -1e30f, m1r = -1e30f, l0r = 0.f, l1r = 0.f;
    float oacc[8][4];
#pragma unroll
    for (int j = 0; j < 8; j++)
#pragma unroll
        for (int q2 = 0; q2 < 4; q2++) oacc[j][q2] = 0.f;

    const int bRowBase = (lane & 7) + ((lane >> 4) << 3);
    const int bCsel = (lane >> 3) & 1;
    const int row0 = wid * 16 + gid;
    const int row1 = row0 + 8;

    for (int t = 0; t <= qt; t++) {
        if (t > 0) {
            if (t < qt) { CP_WAIT1(); } else { CP_WAIT0(); }
            __syncthreads();
        }
        if (t + 2 <= qt) {
            const char* kvs = (const char*)(g_KVp + (bhbase + t + 2) * 24576);
            uint32_t dst = sb + SM_ST + ((t + 2) % 3) * STG;
#pragma unroll
            for (int i = 0; i < 12; i++) {
                uint32_t off = (tid + i * 256) * 16;
                cp_async16(dst + off, kvs + off);
            }
            CP_COMMIT();
        }

        const uint32_t kb = sb + SM_ST + (t % 3) * STG;
        const uint32_t lb = kb + 16384;
        const uint32_t vbse = kb + 32768;

        float sacc[16][4];
#pragma unroll
        for (int j = 0; j < 16; j++)
#pragma unroll
            for (int q2 = 0; q2 < 4; q2++) sacc[j][q2] = 0.f;

#pragma unroll
        for (int kt2 = 0; kt2 < 4; kt2++) {
#pragma unroll
            for (int jt2 = 0; jt2 < 8; jt2++) {
                int r = jt2 * 16 + bRowBase;
                uint32_t kc = kt2 * 2 + bCsel;
                uint32_t bh4[4], bl4[4];
                ldsm4(bh4[0], bh4[1], bh4[2], bh4[3], kb + swz128(r, kc));
                ldsm4(bl4[0], bl4[1], bl4[2], bl4[3], lb + swz128(r, kc));
                mma16816h(sacc[2*jt2],   qh[kt2][0], qh[kt2][1], qh[kt2][2], qh[kt2][3], bh4[0], bh4[1]);
                mma16816h(sacc[2*jt2+1], qh[kt2][0], qh[kt2][1], qh[kt2][2], qh[kt2][3], bh4[2], bh4[3]);
                mma16816h(sacc[2*jt2],   ql[kt2][0], ql[kt2][1], ql[kt2][2], ql[kt2][3], bh4[0], bh4[1]);
                mma16816h(sacc[2*jt2+1], ql[kt2][0], ql[kt2][1], ql[kt2][2], ql[kt2][3], bh4[2], bh4[3]);
                mma16816h(sacc[2*jt2],   qh[kt2][0], qh[kt2][1], qh[kt2][2], qh[kt2][3], bl4[0], bl4[1]);
                mma16816h(sacc[2*jt2+1], qh[kt2][0], qh[kt2][1], qh[kt2][2], qh[kt2][3], bl4[2], bl4[3]);
            }
        }

        if (t == qt) {
#pragma unroll
            for (int j = 0; j < 16; j++) {
                int c0 = j * 8 + qq * 2;
                if (c0 > row0)     sacc[j][0] = -1e30f;
                if (c0 + 1 > row0) sacc[j][1] = -1e30f;
                if (c0 > row1)     sacc[j][2] = -1e30f;
                if (c0 + 1 > row1) sacc[j][3] = -1e30f;
            }
        }

        float mx0 = -1e30f, mx1 = -1e30f;
#pragma unroll
        for (int j = 0; j < 16; j++) {
            mx0 = fmaxf(mx0, fmaxf(sacc[j][0], sacc[j][1]));
            mx1 = fmaxf(mx1, fmaxf(sacc[j][2], sacc[j][3]));
        }
        mx0 = fmaxf(mx0, __shfl_xor_sync(0xffffffffu, mx0, 1));
        mx0 = fmaxf(mx0, __shfl_xor_sync(0xffffffffu, mx0, 2));
        mx1 = fmaxf(mx1, __shfl_xor_sync(0xffffffffu, mx1, 1));
        mx1 = fmaxf(mx1, __shfl_xor_sync(0xffffffffu, mx1, 2));

        float mn0 = fmaxf(m0r, mx0), mn1 = fmaxf(m1r, mx1);
        float cr0 = ex2(m0r - mn0), cr1 = ex2(m1r - mn1);
        float sum0 = 0.f, sum1 = 0.f;
#pragma unroll
        for (int j = 0; j < 16; j++) {
            sacc[j][0] = ex2(sacc[j][0] - mn0);
            sacc[j][1] = ex2(sacc[j][1] - mn0);
            sacc[j][2] = ex2(sacc[j][2] - mn1);
            sacc[j][3] = ex2(sacc[j][3] - mn1);
            sum0 += sacc[j][0] + sacc[j][1];
            sum1 += sacc[j][2] + sacc[j][3];
        }
        sum0 += __shfl_xor_sync(0xffffffffu, sum0, 1);
        sum0 += __shfl_xor_sync(0xffffffffu, sum0, 2);
        sum1 += __shfl_xor_sync(0xffffffffu, sum1, 1);
        sum1 += __shfl_xor_sync(0xffffffffu, sum1, 2);

        l0r = l0r * cr0 + sum0;  m0r = mn0;
        l1r = l1r * cr1 + sum1;  m1r = mn1;
#pragma unroll
        for (int j = 0; j < 8; j++) {
            oacc[j][0] *= cr0; oacc[j][1] *= cr0;
            oacc[j][2] *= cr1; oacc[j][3] *= cr1;
        }

#pragma unroll
        for (int kt2 = 0; kt2 < 8; kt2++) {
            const int jA = 2 * kt2, jB = 2 * kt2 + 1;
            uint32_t ph[4];
            ph[0] = pack_h2(sacc[jA][0], sacc[jA][1]);
            ph[1] = pack_h2(sacc[jA][2], sacc[jA][3]);
            ph[2] = pack_h2(sacc[jB][0], sacc[jB][1]);
            ph[3] = pack_h2(sacc[jB][2], sacc[jB][3]);
#pragma unroll
            for (int nt2 = 0; nt2 < 4; nt2++) {
                int r = nt2 * 16 + bRowBase;
                uint32_t vc = kt2 * 2 + bCsel;
                uint32_t bv[4];
                ldsm4(bv[0], bv[1], bv[2], bv[3], vbse + swzV(r, vc));
                mma16816h(oacc[2*nt2],   ph[0], ph[1], ph[2], ph[3], bv[0], bv[1]);
                mma16816h(oacc[2*nt2+1], ph[0], ph[1], ph[2], ph[3], bv[2], bv[3]);
            }
        }
    }

    // ---- normalize + store single fp16 (pitch D_MODEL) ----
    const float inv0 = 1.0f / l0r, inv1 = 1.0f / l1r;
    const size_t gr0 = (size_t)(b * SEQ + q0 + row0);
    const size_t gr1 = (size_t)(b * SEQ + q0 + row1);
#pragma unroll
    for (int nt = 0; nt < 8; nt++) {
        int col = h * D_HEAD + nt * 8 + qq * 2;
        *(uint32_t*)(g_aoh + gr0 * D_MODEL + col) =
            pack_h2(oacc[nt][0] * inv0, oacc[nt][1] * inv0);
        *(uint32_t*)(g_aoh + gr1 * D_MODEL + col) =
            pack_h2(oacc[nt][2] * inv1, oacc[nt][3] * inv1);
    }
}

// ---------------------------------------------------------------------------
extern "C" void kernel_launch(void* const* d_in, const int* in_sizes, int n_in,
                              void* d_out, int out_size)
{
    const float* x  = (const float*)d_in[0];
    const float* Wq = (const float*)d_in[1];
    const float* Wk = (const float*)d_in[2];
    const float* Wv = (const float*)d_in[3];
    const float* Wo = (const float*)d_in[4];
    float* out = (float*)d_out;

    void *pxh, *paoh, *pwh;
    cudaGetSymbolAddress(&pxh,  g_xh);
    cudaGetSymbolAddress(&paoh, g_aoh);
    cudaGetSymbolAddress(&pwh,  g_wh);

    __half* xh  = (__half*)pxh;
    __half* aoh = (__half*)paoh;
    __half* wh  = (__half*)pwh;

    cudaFuncSetAttribute(gemm_o,
                         cudaFuncAttributeMaxDynamicSharedMemorySize, G_SMEM);
    cudaFuncSetAttribute(gemm_qkv,
                         cudaFuncAttributeMaxDynamicSharedMemorySize, G_SMEM);
    cudaFuncSetAttribute(flash_attn_f16,
                         cudaFuncAttributeMaxDynamicSharedMemorySize, A_SMEM);

    const int total4 = N4X + 4 * N4W;
    convert_all<<<(total4 + 255) / 256, 256>>>(x, Wq, Wk, Wv, Wo);

    dim3 qkvgrid(K3 / BN, M_ROWS / BM);      // (24, 64)
    gemm_qkv<<<qkvgrid, 256, G_SMEM>>>(xh, wh);

    dim3 fgrid(NQT, N_HEADS, B_SZ);          // (16, 16, 4)
    flash_attn_f16<<<fgrid, 256, A_SMEM>>>();

    dim3 ogrid(D_MODEL / BN, M_ROWS / BM);   // (8, 64)
    gemm_o<<<ogrid, 256, G_SMEM>>>(aoh, wh + 3 * (size_t)D_MODEL * D_MODEL, out);
}